// round 12
// baseline (speedup 1.0000x reference)
#include <cuda_runtime.h>
#include <cuda_bf16.h>
#include <math.h>

#define TT 512
#define BB 64
#define EE 256
#define HH 200
#define G4 800
#define CC 20
#define NBD 50   // blocks per direction in LSTM kernel
#define HSL 4    // h-units per block (HH / NBD)
#define KT3 13   // k16-tiles covering HH=200 (pad to 208)
#define HBUF (104 * 72)   // uints per h tile buffer

typedef unsigned int uint;

// ---------------- device scratch (no allocations allowed) ----------------
__device__ uint  d_xh[TT * BB * (EE / 2)];        // LN'd embeddings bf16x2
__device__ uint  d_Gh[2 * TT * G4 * 32];          // gates_x bf16x2 (batch pairs)
__device__ uint  d_hallh[2 * (TT + 1) * NBD * 128]; // h history bf16x2 [dir][slot][sl][u*32+bp]
__device__ float d_logits[BB * TT * CC];          // log_softmax outputs [b][t][c]
__device__ float d_loss[BB];
__device__ unsigned d_flagsp[2][NBD][32];         // flags spread 128B apart

#define HSLOT 6400           // uints per history slot (NBD*128)
#define HDIR  ((TT + 1) * HSLOT)

__device__ __forceinline__ uint pkbf(float lo, float hi) {
    uint r;
    asm("cvt.rn.bf16x2.f32 %0, %1, %2;" : "=r"(r) : "f"(hi), "f"(lo));
    return r;
}
__device__ __forceinline__ float bflo(uint v) { return __uint_as_float(v << 16); }
__device__ __forceinline__ float bfhi(uint v) { return __uint_as_float(v & 0xffff0000u); }
__device__ __forceinline__ float sigf(float x)  { return 1.f / (1.f + __expf(-x)); }
__device__ __forceinline__ float tanhfast(float x) { return 1.f - 2.f / (__expf(2.f * x) + 1.f); }

#define MMA_BF16(ACC, A, B0, B1)                                           \
    asm volatile(                                                          \
        "mma.sync.aligned.m16n8k16.row.col.f32.bf16.bf16.f32 "             \
        "{%0,%1,%2,%3}, {%4,%5,%6,%7}, {%8,%9}, {%0,%1,%2,%3};"            \
        : "+f"((ACC)[0]), "+f"((ACC)[1]), "+f"((ACC)[2]), "+f"((ACC)[3])   \
        : "r"((A)[0]), "r"((A)[1]), "r"((A)[2]), "r"((A)[3]),              \
          "r"(B0), "r"(B1))

#define BAR_SYNC(id, n)   asm volatile("bar.sync %0, %1;"   :: "r"(id), "r"(n) : "memory")
#define BAR_ARRIVE(id, n) asm volatile("bar.arrive %0, %1;" :: "r"(id), "r"(n) : "memory")

// ---------------- K0: init (zero boundary h slots + flags) ----------------
__global__ void k0_init() {
    int tid = threadIdx.x;
    for (int i = tid; i < HSLOT; i += 256) {
        d_hallh[i] = 0u;                          // dir0, slot 0
        d_hallh[HDIR + (size_t)TT * HSLOT + i] = 0u;  // dir1, slot TT
    }
    for (int i = tid; i < 2 * NBD * 32; i += 256) ((unsigned*)d_flagsp)[i] = 0u;
}

// ---------------- K1: embedding + LayerNorm -> bf16x2 (warp per token) ----------------
__global__ void __launch_bounds__(256) k1_embed_ln(
    const int* __restrict__ words, const float* __restrict__ embed,
    const float* __restrict__ gamma, const float* __restrict__ beta)
{
    int wid = threadIdx.x >> 5, lane = threadIdx.x & 31;
    int tok = blockIdx.x * 8 + wid;          // tok = t*64 + b
    int t = tok >> 6, b = tok & 63;
    int word = words[b * TT + t];
    const float4* src = (const float4*)(embed + (size_t)word * EE);
    float4 v0 = src[lane * 2], v1 = src[lane * 2 + 1];
    float s = v0.x + v0.y + v0.z + v0.w + v1.x + v1.y + v1.z + v1.w;
    float q = v0.x*v0.x + v0.y*v0.y + v0.z*v0.z + v0.w*v0.w
            + v1.x*v1.x + v1.y*v1.y + v1.z*v1.z + v1.w*v1.w;
    #pragma unroll
    for (int o = 16; o; o >>= 1) {
        s += __shfl_xor_sync(~0u, s, o);
        q += __shfl_xor_sync(~0u, q, o);
    }
    float mu  = s * (1.f / EE);
    float var = q * (1.f / EE) - mu * mu;
    float rs  = rsqrtf(var + 1e-5f);
    const float4* g4 = (const float4*)gamma;
    const float4* bt4 = (const float4*)beta;
    float4 ga = g4[lane*2], gb = g4[lane*2+1];
    float4 ba = bt4[lane*2], bb = bt4[lane*2+1];
    float o0x = (v0.x-mu)*rs*ga.x + ba.x,  o0y = (v0.y-mu)*rs*ga.y + ba.y;
    float o0z = (v0.z-mu)*rs*ga.z + ba.z,  o0w = (v0.w-mu)*rs*ga.w + ba.w;
    float o1x = (v1.x-mu)*rs*gb.x + bb.x,  o1y = (v1.y-mu)*rs*gb.y + bb.y;
    float o1z = (v1.z-mu)*rs*gb.z + bb.z,  o1w = (v1.w-mu)*rs*gb.w + bb.w;
    uint4 pk;
    pk.x = pkbf(o0x, o0y);  pk.y = pkbf(o0z, o0w);
    pk.z = pkbf(o1x, o1y);  pk.w = pkbf(o1z, o1w);
    *(uint4*)(d_xh + (size_t)tok * 128 + lane * 4) = pk;
}

// ---------------- K2: bf16 tensor-core GEMM, register double-buffered ----------------
__global__ void __launch_bounds__(256) k2_gemm(
    const float* __restrict__ wihf, const float* __restrict__ wihb,
    const float* __restrict__ bf,   const float* __restrict__ bbias)
{
    __shared__ uint As2[128 * 12];   // [m][k/2] bf16x2, stride 12 (8 data + 4 pad)
    __shared__ uint Bs2[64 * 12];

    int tid = threadIdx.x;
    int m0 = blockIdx.y * 128, n0 = blockIdx.x * 64;
    int wid = tid >> 5, lane = tid & 31;
    int wm = wid & 3, wn = wid >> 2;            // warp grid 4 x 2
    int gid = lane >> 2, ctid = lane & 3;

    float acc[2][4][4];
    #pragma unroll
    for (int mi = 0; mi < 2; ++mi)
        #pragma unroll
        for (int ni = 0; ni < 4; ++ni)
            #pragma unroll
            for (int r = 0; r < 4; ++r) acc[mi][ni][r] = 0.f;

    int arow = tid >> 1, apart = tid & 1;
    int brow = tid >> 2, bq = tid & 3;
    int nglob = n0 + brow;
    const float* wrow = (nglob < G4) ? (wihf + (size_t)nglob * EE)
                                     : (wihb + (size_t)(nglob - G4) * EE);

    uint4 aReg = *(const uint4*)(d_xh + (size_t)(m0 + arow) * 128 + apart * 4);
    float4 bReg = *(const float4*)(wrow + bq * 4);

    for (int it = 0; it < 16; ++it) {
        {
            uint* dst = As2 + arow * 12 + apart * 4;
            dst[0] = aReg.x; dst[1] = aReg.y; dst[2] = aReg.z; dst[3] = aReg.w;
            uint* db = Bs2 + brow * 12 + bq * 2;
            db[0] = pkbf(bReg.x, bReg.y);
            db[1] = pkbf(bReg.z, bReg.w);
        }
        __syncthreads();

        if (it + 1 < 16) {
            int k0 = (it + 1) * 16;
            aReg = *(const uint4*)(d_xh + (size_t)(m0 + arow) * 128 + (k0 >> 1) + apart * 4);
            bReg = *(const float4*)(wrow + k0 + bq * 4);
        }

        uint afr[2][4], bfr[4][2];
        #pragma unroll
        for (int mi = 0; mi < 2; ++mi) {
            int mb = wm * 32 + mi * 16;
            const uint* ap = As2 + (mb + gid) * 12 + ctid;
            afr[mi][0] = ap[0];
            afr[mi][1] = ap[8 * 12];
            afr[mi][2] = ap[4];
            afr[mi][3] = ap[8 * 12 + 4];
        }
        #pragma unroll
        for (int ni = 0; ni < 4; ++ni) {
            int nb = wn * 32 + ni * 8;
            const uint* bp = Bs2 + (nb + gid) * 12 + ctid;
            bfr[ni][0] = bp[0];
            bfr[ni][1] = bp[4];
        }
        #pragma unroll
        for (int mi = 0; mi < 2; ++mi)
            #pragma unroll
            for (int ni = 0; ni < 4; ++ni)
                MMA_BF16(acc[mi][ni], afr[mi], bfr[ni][0], bfr[ni][1]);
        __syncthreads();
    }

    #pragma unroll
    for (int mi = 0; mi < 2; ++mi)
        #pragma unroll
        for (int ni = 0; ni < 4; ++ni)
            #pragma unroll
            for (int r = 0; r < 4; ++r) {
                int n = n0 + wn * 32 + ni * 8 + 2 * ctid + (r & 1);
                int dir = (n >= G4) ? 1 : 0;
                int rr = n - dir * G4;
                float val = acc[mi][ni][r] + (dir ? bbias[rr] : bf[rr]);
                float pv = __shfl_xor_sync(~0u, val, 4);   // partner batch b+1
                if ((gid & 1) == 0) {
                    int m = m0 + wm * 32 + mi * 16 + gid + (r >> 1) * 8;
                    int t = m >> 6, b = m & 63;            // b even
                    d_Gh[((size_t)dir * TT * G4 + (size_t)t * G4 + rr) * 32 + (b >> 1)]
                        = pkbf(val, pv);
                }
            }
}

// ---------------- K3: warp-specialized persistent BiLSTM ----------------
// 100 blocks, 256 threads: warps 0-3 compute (R9 mma/act), warps 4-7 loaders.
// Double-buffered h tile + named barriers: loader poll/load overlaps compute tail.
__global__ void __launch_bounds__(256, 1) k3_lstm(
    const float* __restrict__ whhf, const float* __restrict__ whhb,
    const int* __restrict__ seq_len)
{
    extern __shared__ uint hsh2[];            // 2 x [104][72] bf16x2 buffers

    int tid = threadIdx.x;
    int dir = blockIdx.x / NBD;
    int sl  = blockIdx.x % NBD;
    int j0  = sl * HSL;
    const float* whh = dir ? whhb : whhf;

    uint* hbase = d_hallh + (size_t)dir * HDIR;
    unsigned* flg = &d_flagsp[dir][0][0];   // stride 32 u32 per producer

    // zero both buffers (h_0 = 0 incl. own-slice rows; pad rows stay 0 forever)
    for (int i = tid; i < 2 * HBUF; i += 256) hsh2[i] = 0u;
    __syncthreads();

    if (tid < 128) {
        // ================= compute group (warps 0-3) =================
        int wid = tid >> 5, lane = tid & 31;
        int gid = lane >> 2, ctid = lane & 3;
        int u   = gid & 3;            // local hidden unit 0..3
        int q1  = gid >> 2;           // 0: rows {i,g}; 1: rows {f,o}
        int bnw = wid * 16;           // warp batch base
        int b0  = bnw + q1 * 8 + 2 * ctid;

        // persistent bf16 A fragments (k16 tiles; zero-pad k>=200)
        uint aw[KT3][4];
        {
            int rowA = q1 * HH + j0 + u;
            int rowB = (q1 + 2) * HH + j0 + u;
            #pragma unroll
            for (int kt = 0; kt < KT3; ++kt) {
                int kA = kt * 16 + 2 * ctid;
                int kC = kA + 8;
                float a0 = whh[(size_t)rowA * HH + kA];
                float a1 = whh[(size_t)rowA * HH + kA + 1];
                float b0v = whh[(size_t)rowB * HH + kA];
                float b1v = whh[(size_t)rowB * HH + kA + 1];
                float a2 = (kC < HH) ? whh[(size_t)rowA * HH + kC] : 0.f;
                float a3 = (kC + 1 < HH) ? whh[(size_t)rowA * HH + kC + 1] : 0.f;
                float b2v = (kC < HH) ? whh[(size_t)rowB * HH + kC] : 0.f;
                float b3v = (kC + 1 < HH) ? whh[(size_t)rowB * HH + kC + 1] : 0.f;
                aw[kt][0] = pkbf(a0, a1);
                aw[kt][1] = pkbf(b0v, b1v);
                aw[kt][2] = pkbf(a2, a3);
                aw[kt][3] = pkbf(b2v, b3v);
            }
        }

        int len0 = seq_len[b0], len1 = seq_len[b0 + 1];
        float c0 = 0.f, c1 = 0.f, hp0 = 0.f, hp1 = 0.f;
        uint pk = 0u;

        int goff[4];
        #pragma unroll
        for (int q = 0; q < 4; ++q)
            goff[q] = (q * HH + j0 + u) * 32 + (b0 >> 1);
        const uint* Gd = d_Gh + (size_t)dir * TT * G4 * 32;

        uint xg[4];
        {
            int t0 = dir ? (TT - 1) : 0;
            const uint* Gt = Gd + (size_t)t0 * G4 * 32;
            #pragma unroll
            for (int q = 0; q < 4; ++q) xg[q] = __ldcg(Gt + goff[q]);
        }

        for (int st = 0; st < TT; ++st) {
            int t = dir ? (TT - 1 - st) : st;
            int ws = dir ? t : (t + 1);        // history write slot
            int p = st & 1;
            const uint* buf = hsh2 + p * HBUF;

            BAR_SYNC(1 + p, 256);              // READY: h(st) staged in buf p

            // gates(16 x 64) = W @ h
            float acc0[4] = {0.f, 0.f, 0.f, 0.f};
            float acc1[4] = {0.f, 0.f, 0.f, 0.f};
            #pragma unroll
            for (int kt = 0; kt < KT3; ++kt) {
                const uint* hk = buf + (kt * 8 + ctid) * 72;
                uint b00 = hk[bnw + gid];
                uint b01 = hk[4 * 72 + bnw + gid];
                uint b10 = hk[bnw + 8 + gid];
                uint b11 = hk[4 * 72 + bnw + 8 + gid];
                MMA_BF16(acc0, aw[kt], b00, b01);
                MMA_BF16(acc1, aw[kt], b10, b11);
            }

            BAR_ARRIVE(3 + p, 256);            // FREE: buf p reusable (for st+2)

            // exchange gate pairs with partner (lane ^ 16)
            float s0 = q1 ? acc0[0] : acc1[0];
            float s1 = q1 ? acc0[1] : acc1[1];
            float s2 = q1 ? acc0[2] : acc1[2];
            float s3 = q1 ? acc0[3] : acc1[3];
            float o0 = __shfl_xor_sync(~0u, s0, 16);
            float o1 = __shfl_xor_sync(~0u, s1, 16);
            float o2 = __shfl_xor_sync(~0u, s2, 16);
            float o3 = __shfl_xor_sync(~0u, s3, 16);
            float m0 = q1 ? acc1[0] : acc0[0];
            float m1 = q1 ? acc1[1] : acc0[1];
            float m2 = q1 ? acc1[2] : acc0[2];
            float m3 = q1 ? acc1[3] : acc0[3];
            float gi0 = q1 ? o0 : m0,  gf0 = q1 ? m0 : o0;
            float gg0 = q1 ? o2 : m2,  go0 = q1 ? m2 : o2;
            float gi1 = q1 ? o1 : m1,  gf1 = q1 ? m1 : o1;
            float gg1 = q1 ? o3 : m3,  go1 = q1 ? m3 : o3;

            {
                float cn = sigf(gf0 + bflo(xg[1])) * c0
                         + sigf(gi0 + bflo(xg[0])) * tanhfast(gg0 + bflo(xg[2]));
                float hn = sigf(go0 + bflo(xg[3])) * tanhfast(cn);
                bool valid = (t < len0);
                hp0 = valid ? hn : hp0;
                c0  = valid ? cn : c0;
            }
            {
                float cn = sigf(gf1 + bfhi(xg[1])) * c1
                         + sigf(gi1 + bfhi(xg[0])) * tanhfast(gg1 + bfhi(xg[2]));
                float hn = sigf(go1 + bfhi(xg[3])) * tanhfast(cn);
                bool valid = (t < len1);
                hp1 = valid ? hn : hp1;
                c1  = valid ? cn : c1;
            }

            // publish rounded h to the global history
            pk = pkbf(hp0, hp1);
            __stcg(hbase + (size_t)ws * HSLOT + sl * 128 + u * 32 + (b0 >> 1), pk);

            BAR_SYNC(5, 128);                  // compute-only: drain h stores
            if (tid == 0) {
                asm volatile("fence.acq_rel.gpu;" ::: "memory");
                asm volatile("st.relaxed.gpu.u32 [%0], %1;"
                             :: "l"(flg + sl * 32), "r"((unsigned)(st + 1)) : "memory");
            }

            // own slice into NEXT buffer (k-pair pack with partner unit lane^4)
            {
                uint ppk = __shfl_xor_sync(~0u, pk, 4);
                if ((u & 1) == 0) {
                    uint olo = __byte_perm(pk, ppk, 0x5410);
                    uint ohi = __byte_perm(pk, ppk, 0x7632);
                    uint* bufn = hsh2 + (p ^ 1) * HBUF;
                    *(uint2*)&bufn[(2 * sl + (u >> 1)) * 72 + b0] = make_uint2(olo, ohi);
                }
            }

            // prefetch next step's gx
            if (st + 1 < TT) {
                int tn = dir ? (TT - 2 - st) : (st + 1);
                const uint* Gt = Gd + (size_t)tn * G4 * 32;
                #pragma unroll
                for (int q = 0; q < 4; ++q) xg[q] = __ldcg(Gt + goff[q]);
            }
        }
    } else {
        // ================= loader group (warps 4-7) =================
        int ltid = tid - 128;
        int ls2 = ltid >> 1, lhalf = ltid & 1;
        int lslice = ls2 + (ls2 >= sl ? 1 : 0);
        bool loader = (ltid < 2 * (NBD - 1));

        for (int st = 0; st < TT; ++st) {
            int t = dir ? (TT - 1 - st) : st;
            int rs = dir ? (t + 1) : t;        // history read slot
            int p = st & 1;
            uint* bufp = hsh2 + p * HBUF;

            if (st >= 2) BAR_SYNC(3 + p, 256);   // FREE: compute done with buf p @ st-2

            if (loader) {
                unsigned v;
                const unsigned* fp = flg + lslice * 32;
                do {
                    asm volatile("ld.acquire.gpu.u32 %0, [%1];" : "=r"(v) : "l"(fp));
                } while (v < (unsigned)st);
                const uint4* src = (const uint4*)(hbase + (size_t)rs * HSLOT + lslice * 128);
                int r0 = 2 * lslice;
                #pragma unroll
                for (int g = 0; g < 4; ++g) {
                    int co = lhalf * 4 + g;
                    int base = co * 8;
                    uint4 A0 = __ldcg(src + 0 * 8 + co);
                    uint4 A1 = __ldcg(src + 1 * 8 + co);
                    uint4 A2 = __ldcg(src + 2 * 8 + co);
                    uint4 A3 = __ldcg(src + 3 * 8 + co);
                    uint4 o;
                    o.x = __byte_perm(A0.x, A1.x, 0x5410);
                    o.y = __byte_perm(A0.x, A1.x, 0x7632);
                    o.z = __byte_perm(A0.y, A1.y, 0x5410);
                    o.w = __byte_perm(A0.y, A1.y, 0x7632);
                    *(uint4*)&bufp[r0 * 72 + base] = o;
                    o.x = __byte_perm(A0.z, A1.z, 0x5410);
                    o.y = __byte_perm(A0.z, A1.z, 0x7632);
                    o.z = __byte_perm(A0.w, A1.w, 0x5410);
                    o.w = __byte_perm(A0.w, A1.w, 0x7632);
                    *(uint4*)&bufp[r0 * 72 + base + 4] = o;
                    o.x = __byte_perm(A2.x, A3.x, 0x5410);
                    o.y = __byte_perm(A2.x, A3.x, 0x7632);
                    o.z = __byte_perm(A2.y, A3.y, 0x5410);
                    o.w = __byte_perm(A2.y, A3.y, 0x7632);
                    *(uint4*)&bufp[(r0 + 1) * 72 + base] = o;
                    o.x = __byte_perm(A2.z, A3.z, 0x5410);
                    o.y = __byte_perm(A2.z, A3.z, 0x7632);
                    o.z = __byte_perm(A2.w, A3.w, 0x5410);
                    o.w = __byte_perm(A2.w, A3.w, 0x7632);
                    *(uint4*)&bufp[(r0 + 1) * 72 + base + 4] = o;
                }
            }
            BAR_SYNC(1 + p, 256);                // READY: buf p staged
        }
    }
}

// ---------------- K4: FC + log_softmax, f32-staged h (block = 16 tokens) ----------------
#define K4SMEM ((CC * 402 + 16 * 400) * 4)
__global__ void __launch_bounds__(128) k4_fc(
    const float* __restrict__ fcw, const float* __restrict__ fcb)
{
    extern __shared__ float k4s[];
    float* wsh = k4s;                  // CC * 402
    float* hsf = k4s + CC * 402;       // [16 tokens][400 features] f32
    __shared__ float fbsh[CC];
    int tid = threadIdx.x;
    int bid = blockIdx.x;
    int t = bid >> 2, bg = bid & 3, b0 = bg * 16;

    for (int i = tid; i < CC * 400; i += 128) {
        int c = i / 400, j = i % 400;
        wsh[c * 402 + j] = fcw[i];
    }
    if (tid < CC) fbsh[tid] = fcb[tid];

    for (int c = tid; c < 1600; c += 128) {
        int row = c >> 2, part = c & 3;
        int dirr = (row >= HH) ? 1 : 0;
        int jj = row - dirr * HH;
        size_t slot = dirr ? (size_t)t : (size_t)(t + 1);
        size_t addr = (size_t)dirr * HDIR + slot * HSLOT
                    + (jj >> 2) * 128 + (jj & 3) * 32 + (b0 >> 1) + part * 2;
        uint2 v = *(const uint2*)&d_hallh[addr];
        int tokbase = part * 4;
        hsf[(tokbase + 0) * 400 + row] = bflo(v.x);
        hsf[(tokbase + 1) * 400 + row] = bfhi(v.x);
        hsf[(tokbase + 2) * 400 + row] = bflo(v.y);
        hsf[(tokbase + 3) * 400 + row] = bfhi(v.y);
    }
    __syncthreads();

    int w = tid >> 5, lane = tid & 31;
    #pragma unroll
    for (int tk = 0; tk < 4; ++tk) {
        int bloc = w * 4 + tk;
        const float* hrow = hsf + bloc * 400;
        float acc = -1e30f;
        if (lane < CC) {
            acc = fbsh[lane];
            const float* wr = wsh + lane * 402;
            #pragma unroll 4
            for (int j = 0; j < 400; j += 2) {
                float2 hv = *(const float2*)&hrow[j];
                float2 wv = *(const float2*)&wr[j];
                acc += hv.x * wv.x + hv.y * wv.y;
            }
        }
        float m = acc;
        #pragma unroll
        for (int o = 16; o; o >>= 1) m = fmaxf(m, __shfl_xor_sync(~0u, m, o));
        float e = (lane < CC) ? __expf(acc - m) : 0.f;
        #pragma unroll
        for (int o = 16; o; o >>= 1) e += __shfl_xor_sync(~0u, e, o);
        float lse = m + __logf(e);
        if (lane < CC) {
            int b = b0 + bloc;
            d_logits[((size_t)b * TT + t) * CC + lane] = acc - lse;
        }
    }
}

// ---------------- K5: CRF NLL, one warp per batch element ----------------
__global__ void __launch_bounds__(32) k5_crf(
    const int* __restrict__ seq_len, const int* __restrict__ target,
    const float* __restrict__ trans, const float* __restrict__ start,
    const float* __restrict__ endsc)
{
    int b = blockIdx.x;
    int lane = threadIdx.x;
    int c = (lane < CC) ? lane : 0;
    int len = seq_len[b];
    const float* L = d_logits + (size_t)b * TT * CC;
    const int* tg = target + (size_t)b * TT;

    float tcol[CC];
    #pragma unroll
    for (int i = 0; i < CC; ++i) tcol[i] = (lane < CC) ? trans[i * CC + c] : 0.f;

    float alpha = (lane < CC) ? (start[c] + L[c]) : -1e30f;

    for (int t = 1; t < len; ++t) {
        float va[CC];
        #pragma unroll
        for (int i = 0; i < CC; ++i)
            va[i] = __shfl_sync(~0u, alpha, i) + tcol[i];
        float m = va[0];
        #pragma unroll
        for (int i = 1; i < CC; ++i) m = fmaxf(m, va[i]);
        float s = 0.f;
        #pragma unroll
        for (int i = 0; i < CC; ++i) s += __expf(va[i] - m);
        float emit = (lane < CC) ? L[t * CC + c] : 0.f;
        float nw = m + __logf(s) + emit;
        alpha = (lane < CC) ? nw : -1e30f;
    }

    float v = (lane < CC) ? (alpha + endsc[c]) : -1e30f;
    float m = v;
    #pragma unroll
    for (int o = 16; o; o >>= 1) m = fmaxf(m, __shfl_xor_sync(~0u, m, o));
    float s = __expf(v - m);
    if (lane >= CC) s = 0.f;
    #pragma unroll
    for (int o = 16; o; o >>= 1) s += __shfl_xor_sync(~0u, s, o);
    float logZ = m + __logf(s);

    float es = 0.f;
    for (int t = lane; t < len; t += 32) es += L[t * CC + tg[t]];
    float ts = 0.f;
    for (int t = lane; t < len - 1; t += 32) ts += trans[tg[t] * CC + tg[t + 1]];
    float g = es + ts;
    #pragma unroll
    for (int o = 16; o; o >>= 1) g += __shfl_xor_sync(~0u, g, o);
    if (lane == 0) {
        float gold = g + start[tg[0]] + endsc[tg[len - 1]];
        d_loss[b] = logZ - gold;
    }
}

// ---------------- K6: mean reduce ----------------
__global__ void __launch_bounds__(64) k6_mean(float* out) {
    __shared__ float sh[64];
    int tid = threadIdx.x;
    sh[tid] = d_loss[tid];
    __syncthreads();
    for (int o = 32; o; o >>= 1) {
        if (tid < o) sh[tid] += sh[tid + o];
        __syncthreads();
    }
    if (tid == 0) out[0] = sh[0] * (1.f / BB);
}

// ---------------- launch ----------------
extern "C" void kernel_launch(void* const* d_in, const int* in_sizes, int n_in,
                              void* d_out, int out_size) {
    const int*   words   = (const int*)d_in[0];
    const int*   seq_len = (const int*)d_in[1];
    const int*   target  = (const int*)d_in[2];
    const float* embed   = (const float*)d_in[3];
    const float* gamma   = (const float*)d_in[4];
    const float* beta    = (const float*)d_in[5];
    const float* wihf    = (const float*)d_in[6];
    const float* whhf    = (const float*)d_in[7];
    const float* bf      = (const float*)d_in[8];
    const float* wihb    = (const float*)d_in[9];
    const float* whhb    = (const float*)d_in[10];
    const float* bb      = (const float*)d_in[11];
    const float* fcw     = (const float*)d_in[12];
    const float* fcb     = (const float*)d_in[13];
    const float* trans   = (const float*)d_in[14];
    const float* startsc = (const float*)d_in[15];
    const float* endsc   = (const float*)d_in[16];
    float* out = (float*)d_out;

    size_t hsmem = (size_t)(2 * HBUF) * sizeof(uint);   // 59904 B
    cudaFuncSetAttribute(k3_lstm, cudaFuncAttributeMaxDynamicSharedMemorySize,
                         (int)hsmem);
    cudaFuncSetAttribute(k4_fc, cudaFuncAttributeMaxDynamicSharedMemorySize,
                         K4SMEM);

    k0_init<<<1, 256>>>();
    k1_embed_ln<<<TT * BB / 8, 256>>>(words, embed, gamma, beta);
    {
        dim3 g(2 * G4 / 64, TT * BB / 128);   // 25 x 256
        k2_gemm<<<g, 256>>>(wihf, wihb, bf, bb);
    }
    k3_lstm<<<2 * NBD, 256, hsmem>>>(whhf, whhb, seq_len);
    k4_fc<<<TT * 4, 128, K4SMEM>>>(fcw, fcb);
    k5_crf<<<BB, 32>>>(seq_len, target, trans, startsc, endsc);
    k6_mean<<<1, 64>>>(out);
}

// round 13
// speedup vs baseline: 1.0712x; 1.0712x over previous
#include <cuda_runtime.h>
#include <cuda_bf16.h>
#include <math.h>

#define TT 512
#define BB 64
#define EE 256
#define HH 200
#define G4 800
#define CC 20
#define NBD 50   // blocks per direction in LSTM kernel
#define HSL 4    // h-units per block (HH / NBD)
#define KT3 13   // k16-tiles covering HH=200 (pad to 208)

typedef unsigned int uint;

// ---------------- device scratch (no allocations allowed) ----------------
__device__ uint  d_xh[TT * BB * (EE / 2)];        // LN'd embeddings bf16x2
__device__ uint  d_Gh[2 * TT * G4 * 32];          // gates_x bf16x2 (batch pairs)
__device__ uint  d_hallh[2 * (TT + 1) * NBD * 128]; // h history bf16x2 [dir][slot][sl][u*32+bp]
__device__ float d_logits[BB * TT * CC];          // log_softmax outputs [b][t][c]
__device__ float d_loss[BB];
__device__ unsigned d_flagsp[2][NBD][32];         // flags spread 128B apart

#define HSLOT 6400           // uints per history slot (NBD*128)
#define HDIR  ((TT + 1) * HSLOT)

__device__ __forceinline__ uint pkbf(float lo, float hi) {
    uint r;
    asm("cvt.rn.bf16x2.f32 %0, %1, %2;" : "=r"(r) : "f"(hi), "f"(lo));
    return r;
}
__device__ __forceinline__ float bflo(uint v) { return __uint_as_float(v << 16); }
__device__ __forceinline__ float bfhi(uint v) { return __uint_as_float(v & 0xffff0000u); }
__device__ __forceinline__ float sigf(float x)  { return 1.f / (1.f + __expf(-x)); }
__device__ __forceinline__ float tanhfast(float x) { return 1.f - 2.f / (__expf(2.f * x) + 1.f); }

#define MMA_BF16(ACC, A, B0, B1)                                           \
    asm volatile(                                                          \
        "mma.sync.aligned.m16n8k16.row.col.f32.bf16.bf16.f32 "             \
        "{%0,%1,%2,%3}, {%4,%5,%6,%7}, {%8,%9}, {%0,%1,%2,%3};"            \
        : "+f"((ACC)[0]), "+f"((ACC)[1]), "+f"((ACC)[2]), "+f"((ACC)[3])   \
        : "r"((A)[0]), "r"((A)[1]), "r"((A)[2]), "r"((A)[3]),              \
          "r"(B0), "r"(B1))

// ---------------- K0: init (zero boundary h slots + flags) ----------------
__global__ void k0_init() {
    int tid = threadIdx.x;
    for (int i = tid; i < HSLOT; i += 256) {
        d_hallh[i] = 0u;                          // dir0, slot 0
        d_hallh[HDIR + (size_t)TT * HSLOT + i] = 0u;  // dir1, slot TT
    }
    for (int i = tid; i < 2 * NBD * 32; i += 256) ((unsigned*)d_flagsp)[i] = 0u;
}

// ---------------- K1: embedding + LayerNorm -> bf16x2 (warp per token) ----------------
__global__ void __launch_bounds__(256) k1_embed_ln(
    const int* __restrict__ words, const float* __restrict__ embed,
    const float* __restrict__ gamma, const float* __restrict__ beta)
{
    int wid = threadIdx.x >> 5, lane = threadIdx.x & 31;
    int tok = blockIdx.x * 8 + wid;          // tok = t*64 + b
    int t = tok >> 6, b = tok & 63;
    int word = words[b * TT + t];
    const float4* src = (const float4*)(embed + (size_t)word * EE);
    float4 v0 = src[lane * 2], v1 = src[lane * 2 + 1];
    float s = v0.x + v0.y + v0.z + v0.w + v1.x + v1.y + v1.z + v1.w;
    float q = v0.x*v0.x + v0.y*v0.y + v0.z*v0.z + v0.w*v0.w
            + v1.x*v1.x + v1.y*v1.y + v1.z*v1.z + v1.w*v1.w;
    #pragma unroll
    for (int o = 16; o; o >>= 1) {
        s += __shfl_xor_sync(~0u, s, o);
        q += __shfl_xor_sync(~0u, q, o);
    }
    float mu  = s * (1.f / EE);
    float var = q * (1.f / EE) - mu * mu;
    float rs  = rsqrtf(var + 1e-5f);
    const float4* g4 = (const float4*)gamma;
    const float4* bt4 = (const float4*)beta;
    float4 ga = g4[lane*2], gb = g4[lane*2+1];
    float4 ba = bt4[lane*2], bb = bt4[lane*2+1];
    float o0x = (v0.x-mu)*rs*ga.x + ba.x,  o0y = (v0.y-mu)*rs*ga.y + ba.y;
    float o0z = (v0.z-mu)*rs*ga.z + ba.z,  o0w = (v0.w-mu)*rs*ga.w + ba.w;
    float o1x = (v1.x-mu)*rs*gb.x + bb.x,  o1y = (v1.y-mu)*rs*gb.y + bb.y;
    float o1z = (v1.z-mu)*rs*gb.z + bb.z,  o1w = (v1.w-mu)*rs*gb.w + bb.w;
    uint4 pk;
    pk.x = pkbf(o0x, o0y);  pk.y = pkbf(o0z, o0w);
    pk.z = pkbf(o1x, o1y);  pk.w = pkbf(o1z, o1w);
    *(uint4*)(d_xh + (size_t)tok * 128 + lane * 4) = pk;
}

// ---------------- K2: bf16 TC GEMM, double-buffered + staged coalesced epilogue ----------------
__global__ void __launch_bounds__(256) k2_gemm(
    const float* __restrict__ wihf, const float* __restrict__ wihb,
    const float* __restrict__ bf,   const float* __restrict__ bbias)
{
    __shared__ uint As2[2][128 * 12];   // [buf][m][k/2] bf16x2
    __shared__ uint Bs2[2][64 * 12];
    __shared__ uint stage[64 * 68];     // epilogue staging [n_local][tl*32+bp], stride 68

    int tid = threadIdx.x;
    int m0 = blockIdx.y * 128, n0 = blockIdx.x * 64;
    int wid = tid >> 5, lane = tid & 31;
    int wm = wid & 3, wn = wid >> 2;            // warp grid 4 x 2
    int gid = lane >> 2, ctid = lane & 3;

    float acc[2][4][4];
    #pragma unroll
    for (int mi = 0; mi < 2; ++mi)
        #pragma unroll
        for (int ni = 0; ni < 4; ++ni)
            #pragma unroll
            for (int r = 0; r < 4; ++r) acc[mi][ni][r] = 0.f;

    int arow = tid >> 1, apart = tid & 1;
    int brow = tid >> 2, bq = tid & 3;
    int nglob = n0 + brow;
    const float* wrow = (nglob < G4) ? (wihf + (size_t)nglob * EE)
                                     : (wihb + (size_t)(nglob - G4) * EE);

    // prologue: slab 0 -> buf 0
    {
        uint4 aReg = *(const uint4*)(d_xh + (size_t)(m0 + arow) * 128 + apart * 4);
        float4 bReg = *(const float4*)(wrow + bq * 4);
        uint* dst = As2[0] + arow * 12 + apart * 4;
        dst[0] = aReg.x; dst[1] = aReg.y; dst[2] = aReg.z; dst[3] = aReg.w;
        uint* db = Bs2[0] + brow * 12 + bq * 2;
        db[0] = pkbf(bReg.x, bReg.y);
        db[1] = pkbf(bReg.z, bReg.w);
    }
    __syncthreads();

    for (int it = 0; it < 16; ++it) {
        int p = it & 1;

        // fragments from buf p
        uint afr[2][4], bfr[4][2];
        #pragma unroll
        for (int mi = 0; mi < 2; ++mi) {
            int mb = wm * 32 + mi * 16;
            const uint* ap = As2[p] + (mb + gid) * 12 + ctid;
            afr[mi][0] = ap[0];
            afr[mi][1] = ap[8 * 12];
            afr[mi][2] = ap[4];
            afr[mi][3] = ap[8 * 12 + 4];
        }
        #pragma unroll
        for (int ni = 0; ni < 4; ++ni) {
            int nb = wn * 32 + ni * 8;
            const uint* bp = Bs2[p] + (nb + gid) * 12 + ctid;
            bfr[ni][0] = bp[0];
            bfr[ni][1] = bp[4];
        }

        // issue next slab's LDG early (latency hides under the mma)
        uint4 aReg;
        float4 bReg;
        if (it + 1 < 16) {
            int k0 = (it + 1) * 16;
            aReg = *(const uint4*)(d_xh + (size_t)(m0 + arow) * 128 + (k0 >> 1) + apart * 4);
            bReg = *(const float4*)(wrow + k0 + bq * 4);
        }

        #pragma unroll
        for (int mi = 0; mi < 2; ++mi)
            #pragma unroll
            for (int ni = 0; ni < 4; ++ni)
                MMA_BF16(acc[mi][ni], afr[mi], bfr[ni][0], bfr[ni][1]);

        if (it + 1 < 16) {
            uint* dst = As2[p ^ 1] + arow * 12 + apart * 4;
            dst[0] = aReg.x; dst[1] = aReg.y; dst[2] = aReg.z; dst[3] = aReg.w;
            uint* db = Bs2[p ^ 1] + brow * 12 + bq * 2;
            db[0] = pkbf(bReg.x, bReg.y);
            db[1] = pkbf(bReg.z, bReg.w);
        }
        __syncthreads();
    }

    // epilogue phase 1: bias + batch-pair pack -> smem staging (conflict-free stride 68)
    #pragma unroll
    for (int mi = 0; mi < 2; ++mi)
        #pragma unroll
        for (int ni = 0; ni < 4; ++ni)
            #pragma unroll
            for (int r = 0; r < 4; ++r) {
                int n_local = wn * 32 + ni * 8 + 2 * ctid + (r & 1);
                int n = n0 + n_local;
                int dir = (n >= G4) ? 1 : 0;
                int rr = n - dir * G4;
                float val = acc[mi][ni][r] + (dir ? bbias[rr] : bf[rr]);
                float pv = __shfl_xor_sync(~0u, val, 4);   // partner batch b+1
                if ((gid & 1) == 0) {
                    int off = wm * 32 + mi * 16 + gid + (r >> 1) * 8;   // 0..127
                    int tl = off >> 6, bp = (off & 63) >> 1;
                    stage[n_local * 68 + tl * 32 + bp] = pkbf(val, pv);
                }
            }
    __syncthreads();

    // epilogue phase 2: coalesced STG.128 writeback
    {
        int t0 = m0 >> 6;
        int row = tid >> 2, ch = tid & 3;
        int n = n0 + row;
        int dir = (n >= G4) ? 1 : 0;
        int rr = n - dir * G4;
        #pragma unroll
        for (int j = 0; j < 4; ++j) {
            int off = ch * 16 + j * 4;          // 0..63 within row
            int tl = off >> 5, bp = off & 31;
            uint4 v = *(const uint4*)&stage[row * 68 + off];
            *(uint4*)&d_Gh[((size_t)dir * TT * G4 + (size_t)(t0 + tl) * G4 + rr) * 32 + bp] = v;
        }
    }
}

// ---------------- K3: persistent BiLSTM, bf16 tensor-core recurrence (R9/R11) ----------------
__global__ void __launch_bounds__(128, 1) k3_lstm(
    const float* __restrict__ whhf, const float* __restrict__ whhb,
    const int* __restrict__ seq_len)
{
    extern __shared__ uint hsh2[];            // [104][72] bf16x2 (k-pair, n) 29952 B

    int tid = threadIdx.x;
    int dir = blockIdx.x / NBD;
    int sl  = blockIdx.x % NBD;
    int j0  = sl * HSL;
    const float* whh = dir ? whhb : whhf;

    int wid = tid >> 5, lane = tid & 31;
    int gid = lane >> 2, ctid = lane & 3;
    int u   = gid & 3;            // local hidden unit 0..3
    int q1  = gid >> 2;           // 0: rows {i,g}; 1: rows {f,o}
    int bnw = wid * 16;           // warp batch base
    int b0  = bnw + q1 * 8 + 2 * ctid;   // this thread's batch pair (b0, b0+1)

    // persistent bf16 A fragments (k16 tiles; zero-pad k>=200)
    uint aw[KT3][4];
    {
        int rowA = q1 * HH + j0 + u;         // mma row gid   -> gate q1
        int rowB = (q1 + 2) * HH + j0 + u;   // mma row gid+8 -> gate q1+2
        #pragma unroll
        for (int kt = 0; kt < KT3; ++kt) {
            int kA = kt * 16 + 2 * ctid;
            int kC = kA + 8;
            float a0 = whh[(size_t)rowA * HH + kA];
            float a1 = whh[(size_t)rowA * HH + kA + 1];
            float b0v = whh[(size_t)rowB * HH + kA];
            float b1v = whh[(size_t)rowB * HH + kA + 1];
            float a2 = (kC < HH) ? whh[(size_t)rowA * HH + kC] : 0.f;
            float a3 = (kC + 1 < HH) ? whh[(size_t)rowA * HH + kC + 1] : 0.f;
            float b2v = (kC < HH) ? whh[(size_t)rowB * HH + kC] : 0.f;
            float b3v = (kC + 1 < HH) ? whh[(size_t)rowB * HH + kC + 1] : 0.f;
            aw[kt][0] = pkbf(a0, a1);
            aw[kt][1] = pkbf(b0v, b1v);
            aw[kt][2] = pkbf(a2, a3);
            aw[kt][3] = pkbf(b2v, b3v);
        }
    }

    // zero the pad rows 100..103 (k 200..207) once
    for (int i = tid; i < 4 * 72; i += 128) hsh2[100 * 72 + i] = 0u;

    int len0 = seq_len[b0], len1 = seq_len[b0 + 1];
    float c0 = 0.f, c1 = 0.f, hp0 = 0.f, hp1 = 0.f;
    uint pk = 0u;                 // packed bf16x2 (hp0 lo, hp1 hi)

    uint* hbase = d_hallh + (size_t)dir * HDIR;
    unsigned* flg = &d_flagsp[dir][0][0];   // stride 32 u32 per producer

    // loader assignment: 2 threads per foreign slice
    int ls2 = tid >> 1, lhalf = tid & 1;
    int lslice = ls2 + (ls2 >= sl ? 1 : 0);
    bool loader = (tid < 2 * (NBD - 1));

    // gx offsets (gates i,f,g,o), uint units within a t-slab of G4*32
    int goff[4];
    #pragma unroll
    for (int q = 0; q < 4; ++q)
        goff[q] = (q * HH + j0 + u) * 32 + (b0 >> 1);

    const uint* Gd = d_Gh + (size_t)dir * TT * G4 * 32;

    // preload gx for st=0
    uint xg[4];
    {
        int t0 = dir ? (TT - 1) : 0;
        const uint* Gt = Gd + (size_t)t0 * G4 * 32;
        #pragma unroll
        for (int q = 0; q < 4; ++q) xg[q] = __ldcg(Gt + goff[q]);
    }

    for (int st = 0; st < TT; ++st) {
        int t = dir ? (TT - 1 - st) : st;
        int rs = dir ? (t + 1) : t;        // read slot (h of previous step)
        int ws = dir ? t : (t + 1);        // write slot (h of this step)

        // own slice: k-pair pack with partner unit (lane^4), even-u stores
        {
            uint ppk = __shfl_xor_sync(~0u, pk, 4);
            if ((u & 1) == 0) {
                uint olo = __byte_perm(pk, ppk, 0x5410);   // col b0
                uint ohi = __byte_perm(pk, ppk, 0x7632);   // col b0+1
                *(uint2*)&hsh2[(2 * sl + (u >> 1)) * 72 + b0] = make_uint2(olo, ohi);
            }
        }

        // foreign slices: poll producer flag, load bf16 slice, PRMT k-repack
        if (loader) {
            unsigned v;
            const unsigned* fp = flg + lslice * 32;
            do {
                asm volatile("ld.acquire.gpu.u32 %0, [%1];" : "=r"(v) : "l"(fp));
            } while (v < (unsigned)st);
            const uint4* src = (const uint4*)(hbase + (size_t)rs * HSLOT + lslice * 128);
            int r0 = 2 * lslice;
            #pragma unroll
            for (int g = 0; g < 4; ++g) {
                int co = lhalf * 4 + g;          // chunk-in-unit (batch group)
                int base = co * 8;               // batch base (col)
                uint4 A0 = __ldcg(src + 0 * 8 + co);   // u0
                uint4 A1 = __ldcg(src + 1 * 8 + co);   // u1
                uint4 A2 = __ldcg(src + 2 * 8 + co);   // u2
                uint4 A3 = __ldcg(src + 3 * 8 + co);   // u3
                uint4 o;
                o.x = __byte_perm(A0.x, A1.x, 0x5410);
                o.y = __byte_perm(A0.x, A1.x, 0x7632);
                o.z = __byte_perm(A0.y, A1.y, 0x5410);
                o.w = __byte_perm(A0.y, A1.y, 0x7632);
                *(uint4*)&hsh2[r0 * 72 + base] = o;
                o.x = __byte_perm(A0.z, A1.z, 0x5410);
                o.y = __byte_perm(A0.z, A1.z, 0x7632);
                o.z = __byte_perm(A0.w, A1.w, 0x5410);
                o.w = __byte_perm(A0.w, A1.w, 0x7632);
                *(uint4*)&hsh2[r0 * 72 + base + 4] = o;
                o.x = __byte_perm(A2.x, A3.x, 0x5410);
                o.y = __byte_perm(A2.x, A3.x, 0x7632);
                o.z = __byte_perm(A2.y, A3.y, 0x5410);
                o.w = __byte_perm(A2.y, A3.y, 0x7632);
                *(uint4*)&hsh2[(r0 + 1) * 72 + base] = o;
                o.x = __byte_perm(A2.z, A3.z, 0x5410);
                o.y = __byte_perm(A2.z, A3.z, 0x7632);
                o.z = __byte_perm(A2.w, A3.w, 0x5410);
                o.w = __byte_perm(A2.w, A3.w, 0x7632);
                *(uint4*)&hsh2[(r0 + 1) * 72 + base + 4] = o;
            }
        }
        __syncthreads();

        // gates(16 x 64) = W @ h  via 2 n-tiles x 13 k16-tiles of m16n8k16
        float acc0[4] = {0.f, 0.f, 0.f, 0.f};
        float acc1[4] = {0.f, 0.f, 0.f, 0.f};
        #pragma unroll
        for (int kt = 0; kt < KT3; ++kt) {
            const uint* hk = hsh2 + (kt * 8 + ctid) * 72;
            uint b00 = hk[bnw + gid];
            uint b01 = hk[4 * 72 + bnw + gid];
            uint b10 = hk[bnw + 8 + gid];
            uint b11 = hk[4 * 72 + bnw + 8 + gid];
            MMA_BF16(acc0, aw[kt], b00, b01);
            MMA_BF16(acc1, aw[kt], b10, b11);
        }

        // exchange gate pairs with partner (lane ^ 16)
        float s0 = q1 ? acc0[0] : acc1[0];
        float s1 = q1 ? acc0[1] : acc1[1];
        float s2 = q1 ? acc0[2] : acc1[2];
        float s3 = q1 ? acc0[3] : acc1[3];
        float o0 = __shfl_xor_sync(~0u, s0, 16);
        float o1 = __shfl_xor_sync(~0u, s1, 16);
        float o2 = __shfl_xor_sync(~0u, s2, 16);
        float o3 = __shfl_xor_sync(~0u, s3, 16);
        float m0 = q1 ? acc1[0] : acc0[0];
        float m1 = q1 ? acc1[1] : acc0[1];
        float m2 = q1 ? acc1[2] : acc0[2];
        float m3 = q1 ? acc1[3] : acc0[3];
        float gi0 = q1 ? o0 : m0,  gf0 = q1 ? m0 : o0;
        float gg0 = q1 ? o2 : m2,  go0 = q1 ? m2 : o2;
        float gi1 = q1 ? o1 : m1,  gf1 = q1 ? m1 : o1;
        float gg1 = q1 ? o3 : m3,  go1 = q1 ? m3 : o3;

        // activations + packed-sequence masking (gx from prefetched bf16x2)
        {
            float cn = sigf(gf0 + bflo(xg[1])) * c0
                     + sigf(gi0 + bflo(xg[0])) * tanhfast(gg0 + bflo(xg[2]));
            float hn = sigf(go0 + bflo(xg[3])) * tanhfast(cn);
            bool valid = (t < len0);
            hp0 = valid ? hn : hp0;
            c0  = valid ? cn : c0;
        }
        {
            float cn = sigf(gf1 + bfhi(xg[1])) * c1
                     + sigf(gi1 + bfhi(xg[0])) * tanhfast(gg1 + bfhi(xg[2]));
            float hn = sigf(go1 + bfhi(xg[3])) * tanhfast(cn);
            bool valid = (t < len1);
            hp1 = valid ? hn : hp1;
            c1  = valid ? cn : c1;
        }

        // broadcast rounded h into the history (this IS the record for k4 too)
        pk = pkbf(hp0, hp1);
        __stcg(hbase + (size_t)ws * HSLOT + sl * 128 + u * 32 + (b0 >> 1), pk);

        __syncthreads();
        if (tid == 0) {
            asm volatile("fence.acq_rel.gpu;" ::: "memory");
            asm volatile("st.relaxed.gpu.u32 [%0], %1;"
                         :: "l"(flg + sl * 32), "r"((unsigned)(st + 1)) : "memory");
        }

        // prefetch next step's gx (off the critical path: ~a full step of slack)
        if (st + 1 < TT) {
            int tn = dir ? (TT - 2 - st) : (st + 1);
            const uint* Gt = Gd + (size_t)tn * G4 * 32;
            #pragma unroll
            for (int q = 0; q < 4; ++q) xg[q] = __ldcg(Gt + goff[q]);
        }
    }
}

// ---------------- K4: FC + log_softmax, f32-staged h (block = 16 tokens) ----------------
#define K4SMEM ((CC * 402 + 16 * 400) * 4)
__global__ void __launch_bounds__(128) k4_fc(
    const float* __restrict__ fcw, const float* __restrict__ fcb)
{
    extern __shared__ float k4s[];
    float* wsh = k4s;                  // CC * 402
    float* hsf = k4s + CC * 402;       // [16 tokens][400 features] f32
    __shared__ float fbsh[CC];
    int tid = threadIdx.x;
    int bid = blockIdx.x;
    int t = bid >> 2, bg = bid & 3, b0 = bg * 16;

    for (int i = tid; i < CC * 400; i += 128) {
        int c = i / 400, j = i % 400;
        wsh[c * 402 + j] = fcw[i];
    }
    if (tid < CC) fbsh[tid] = fcb[tid];

    for (int c = tid; c < 1600; c += 128) {
        int row = c >> 2, part = c & 3;
        int dirr = (row >= HH) ? 1 : 0;
        int jj = row - dirr * HH;
        size_t slot = dirr ? (size_t)t : (size_t)(t + 1);
        size_t addr = (size_t)dirr * HDIR + slot * HSLOT
                    + (jj >> 2) * 128 + (jj & 3) * 32 + (b0 >> 1) + part * 2;
        uint2 v = *(const uint2*)&d_hallh[addr];
        int tokbase = part * 4;
        hsf[(tokbase + 0) * 400 + row] = bflo(v.x);
        hsf[(tokbase + 1) * 400 + row] = bfhi(v.x);
        hsf[(tokbase + 2) * 400 + row] = bflo(v.y);
        hsf[(tokbase + 3) * 400 + row] = bfhi(v.y);
    }
    __syncthreads();

    int w = tid >> 5, lane = tid & 31;
    #pragma unroll
    for (int tk = 0; tk < 4; ++tk) {
        int bloc = w * 4 + tk;
        const float* hrow = hsf + bloc * 400;
        float acc = -1e30f;
        if (lane < CC) {
            acc = fbsh[lane];
            const float* wr = wsh + lane * 402;
            #pragma unroll 4
            for (int j = 0; j < 400; j += 2) {
                float2 hv = *(const float2*)&hrow[j];
                float2 wv = *(const float2*)&wr[j];
                acc += hv.x * wv.x + hv.y * wv.y;
            }
        }
        float m = acc;
        #pragma unroll
        for (int o = 16; o; o >>= 1) m = fmaxf(m, __shfl_xor_sync(~0u, m, o));
        float e = (lane < CC) ? __expf(acc - m) : 0.f;
        #pragma unroll
        for (int o = 16; o; o >>= 1) e += __shfl_xor_sync(~0u, e, o);
        float lse = m + __logf(e);
        if (lane < CC) {
            int b = b0 + bloc;
            d_logits[((size_t)b * TT + t) * CC + lane] = acc - lse;
        }
    }
}

// ---------------- K5: CRF NLL, one warp per batch element ----------------
__global__ void __launch_bounds__(32) k5_crf(
    const int* __restrict__ seq_len, const int* __restrict__ target,
    const float* __restrict__ trans, const float* __restrict__ start,
    const float* __restrict__ endsc)
{
    int b = blockIdx.x;
    int lane = threadIdx.x;
    int c = (lane < CC) ? lane : 0;
    int len = seq_len[b];
    const float* L = d_logits + (size_t)b * TT * CC;
    const int* tg = target + (size_t)b * TT;

    float tcol[CC];
    #pragma unroll
    for (int i = 0; i < CC; ++i) tcol[i] = (lane < CC) ? trans[i * CC + c] : 0.f;

    float alpha = (lane < CC) ? (start[c] + L[c]) : -1e30f;

    for (int t = 1; t < len; ++t) {
        float va[CC];
        #pragma unroll
        for (int i = 0; i < CC; ++i)
            va[i] = __shfl_sync(~0u, alpha, i) + tcol[i];
        float m = va[0];
        #pragma unroll
        for (int i = 1; i < CC; ++i) m = fmaxf(m, va[i]);
        float s = 0.f;
        #pragma unroll
        for (int i = 0; i < CC; ++i) s += __expf(va[i] - m);
        float emit = (lane < CC) ? L[t * CC + c] : 0.f;
        float nw = m + __logf(s) + emit;
        alpha = (lane < CC) ? nw : -1e30f;
    }

    float v = (lane < CC) ? (alpha + endsc[c]) : -1e30f;
    float m = v;
    #pragma unroll
    for (int o = 16; o; o >>= 1) m = fmaxf(m, __shfl_xor_sync(~0u, m, o));
    float s = __expf(v - m);
    if (lane >= CC) s = 0.f;
    #pragma unroll
    for (int o = 16; o; o >>= 1) s += __shfl_xor_sync(~0u, s, o);
    float logZ = m + __logf(s);

    float es = 0.f;
    for (int t = lane; t < len; t += 32) es += L[t * CC + tg[t]];
    float ts = 0.f;
    for (int t = lane; t < len - 1; t += 32) ts += trans[tg[t] * CC + tg[t + 1]];
    float g = es + ts;
    #pragma unroll
    for (int o = 16; o; o >>= 1) g += __shfl_xor_sync(~0u, g, o);
    if (lane == 0) {
        float gold = g + start[tg[0]] + endsc[tg[len - 1]];
        d_loss[b] = logZ - gold;
    }
}

// ---------------- K6: mean reduce ----------------
__global__ void __launch_bounds__(64) k6_mean(float* out) {
    __shared__ float sh[64];
    int tid = threadIdx.x;
    sh[tid] = d_loss[tid];
    __syncthreads();
    for (int o = 32; o; o >>= 1) {
        if (tid < o) sh[tid] += sh[tid + o];
        __syncthreads();
    }
    if (tid == 0) out[0] = sh[0] * (1.f / BB);
}

// ---------------- launch ----------------
extern "C" void kernel_launch(void* const* d_in, const int* in_sizes, int n_in,
                              void* d_out, int out_size) {
    const int*   words   = (const int*)d_in[0];
    const int*   seq_len = (const int*)d_in[1];
    const int*   target  = (const int*)d_in[2];
    const float* embed   = (const float*)d_in[3];
    const float* gamma   = (const float*)d_in[4];
    const float* beta    = (const float*)d_in[5];
    const float* wihf    = (const float*)d_in[6];
    const float* whhf    = (const float*)d_in[7];
    const float* bf      = (const float*)d_in[8];
    const float* wihb    = (const float*)d_in[9];
    const float* whhb    = (const float*)d_in[10];
    const float* bb      = (const float*)d_in[11];
    const float* fcw     = (const float*)d_in[12];
    const float* fcb     = (const float*)d_in[13];
    const float* trans   = (const float*)d_in[14];
    const float* startsc = (const float*)d_in[15];
    const float* endsc   = (const float*)d_in[16];
    float* out = (float*)d_out;

    size_t hsmem = (size_t)(104 * 72) * sizeof(uint);   // 29952 B
    cudaFuncSetAttribute(k3_lstm, cudaFuncAttributeMaxDynamicSharedMemorySize,
                         (int)hsmem);
    cudaFuncSetAttribute(k4_fc, cudaFuncAttributeMaxDynamicSharedMemorySize,
                         K4SMEM);

    k0_init<<<1, 256>>>();
    k1_embed_ln<<<TT * BB / 8, 256>>>(words, embed, gamma, beta);
    {
        dim3 g(2 * G4 / 64, TT * BB / 128);   // 25 x 256
        k2_gemm<<<g, 256>>>(wihf, wihb, bf, bb);
    }
    k3_lstm<<<2 * NBD, 128, hsmem>>>(whhf, whhb, seq_len);
    k4_fc<<<TT * 4, 128, K4SMEM>>>(fcw, fcb);
    k5_crf<<<BB, 32>>>(seq_len, target, trans, startsc, endsc);
    k6_mean<<<1, 64>>>(out);
}

// round 14
// speedup vs baseline: 1.1174x; 1.0431x over previous
#include <cuda_runtime.h>
#include <cuda_bf16.h>
#include <math.h>

#define TT 512
#define BB 64
#define EE 256
#define HH 200
#define G4 800
#define CC 20
#define NBD 50   // blocks per direction in LSTM kernel
#define HSL 4    // h-units per block (HH / NBD)
#define KT3 13   // k16-tiles covering HH=200 (pad to 208)

typedef unsigned int uint;

// ---------------- device scratch (no allocations allowed) ----------------
__device__ uint  d_xh[TT * BB * (EE / 2)];        // LN'd embeddings bf16x2
__device__ uint  d_Gh[2 * TT * G4 * 32];          // gates_x bf16x2 (batch pairs)
__device__ uint  d_hallh[2 * (TT + 1) * NBD * 128]; // h history bf16x2 [dir][slot][sl][u*32+bp]
__device__ float d_logits[BB * TT * CC];          // log_softmax outputs [b][t][c]
__device__ float d_loss[BB];
__device__ unsigned d_flagsp[2][NBD][32];         // flags spread 128B apart

#define HSLOT 6400           // uints per history slot (NBD*128)
#define HDIR  ((TT + 1) * HSLOT)

__device__ __forceinline__ uint pkbf(float lo, float hi) {
    uint r;
    asm("cvt.rn.bf16x2.f32 %0, %1, %2;" : "=r"(r) : "f"(hi), "f"(lo));
    return r;
}
__device__ __forceinline__ float bflo(uint v) { return __uint_as_float(v << 16); }
__device__ __forceinline__ float bfhi(uint v) { return __uint_as_float(v & 0xffff0000u); }
__device__ __forceinline__ float sigf(float x)  { return 1.f / (1.f + __expf(-x)); }
__device__ __forceinline__ float tanhfast(float x) { return 1.f - 2.f / (__expf(2.f * x) + 1.f); }

#define MMA_BF16(ACC, A, B0, B1)                                           \
    asm volatile(                                                          \
        "mma.sync.aligned.m16n8k16.row.col.f32.bf16.bf16.f32 "             \
        "{%0,%1,%2,%3}, {%4,%5,%6,%7}, {%8,%9}, {%0,%1,%2,%3};"            \
        : "+f"((ACC)[0]), "+f"((ACC)[1]), "+f"((ACC)[2]), "+f"((ACC)[3])   \
        : "r"((A)[0]), "r"((A)[1]), "r"((A)[2]), "r"((A)[3]),              \
          "r"(B0), "r"(B1))

// ---------------- K1: embedding + LayerNorm -> bf16x2; block 0 also inits ----------------
__global__ void __launch_bounds__(256) k1_embed_ln(
    const int* __restrict__ words, const float* __restrict__ embed,
    const float* __restrict__ gamma, const float* __restrict__ beta)
{
    // init (formerly k0): boundary h slots + flags, done by block 0
    if (blockIdx.x == 0) {
        int t0 = threadIdx.x;
        for (int i = t0; i < HSLOT; i += 256) {
            d_hallh[i] = 0u;                              // dir0, slot 0
            d_hallh[HDIR + (size_t)TT * HSLOT + i] = 0u;  // dir1, slot TT
        }
        for (int i = t0; i < 2 * NBD * 32; i += 256) ((unsigned*)d_flagsp)[i] = 0u;
    }

    int wid = threadIdx.x >> 5, lane = threadIdx.x & 31;
    int tok = blockIdx.x * 8 + wid;          // tok = t*64 + b
    int t = tok >> 6, b = tok & 63;
    int word = words[b * TT + t];
    const float4* src = (const float4*)(embed + (size_t)word * EE);
    float4 v0 = src[lane * 2], v1 = src[lane * 2 + 1];
    float s = v0.x + v0.y + v0.z + v0.w + v1.x + v1.y + v1.z + v1.w;
    float q = v0.x*v0.x + v0.y*v0.y + v0.z*v0.z + v0.w*v0.w
            + v1.x*v1.x + v1.y*v1.y + v1.z*v1.z + v1.w*v1.w;
    #pragma unroll
    for (int o = 16; o; o >>= 1) {
        s += __shfl_xor_sync(~0u, s, o);
        q += __shfl_xor_sync(~0u, q, o);
    }
    float mu  = s * (1.f / EE);
    float var = q * (1.f / EE) - mu * mu;
    float rs  = rsqrtf(var + 1e-5f);
    const float4* g4 = (const float4*)gamma;
    const float4* bt4 = (const float4*)beta;
    float4 ga = g4[lane*2], gb = g4[lane*2+1];
    float4 ba = bt4[lane*2], bb = bt4[lane*2+1];
    float o0x = (v0.x-mu)*rs*ga.x + ba.x,  o0y = (v0.y-mu)*rs*ga.y + ba.y;
    float o0z = (v0.z-mu)*rs*ga.z + ba.z,  o0w = (v0.w-mu)*rs*ga.w + ba.w;
    float o1x = (v1.x-mu)*rs*gb.x + bb.x,  o1y = (v1.y-mu)*rs*gb.y + bb.y;
    float o1z = (v1.z-mu)*rs*gb.z + bb.z,  o1w = (v1.w-mu)*rs*gb.w + bb.w;
    uint4 pk;
    pk.x = pkbf(o0x, o0y);  pk.y = pkbf(o0z, o0w);
    pk.z = pkbf(o1x, o1y);  pk.w = pkbf(o1z, o1w);
    *(uint4*)(d_xh + (size_t)tok * 128 + lane * 4) = pk;
}

// ---------------- K2: bf16 TC GEMM, double-buffered + staged coalesced epilogue ----------------
__global__ void __launch_bounds__(256) k2_gemm(
    const float* __restrict__ wihf, const float* __restrict__ wihb,
    const float* __restrict__ bf,   const float* __restrict__ bbias)
{
    __shared__ uint As2[2][128 * 12];   // [buf][m][k/2] bf16x2
    __shared__ uint Bs2[2][64 * 12];
    __shared__ uint stage[64 * 68];     // epilogue staging [n_local][tl*32+bp], stride 68

    int tid = threadIdx.x;
    int m0 = blockIdx.y * 128, n0 = blockIdx.x * 64;
    int wid = tid >> 5, lane = tid & 31;
    int wm = wid & 3, wn = wid >> 2;            // warp grid 4 x 2
    int gid = lane >> 2, ctid = lane & 3;

    float acc[2][4][4];
    #pragma unroll
    for (int mi = 0; mi < 2; ++mi)
        #pragma unroll
        for (int ni = 0; ni < 4; ++ni)
            #pragma unroll
            for (int r = 0; r < 4; ++r) acc[mi][ni][r] = 0.f;

    int arow = tid >> 1, apart = tid & 1;
    int brow = tid >> 2, bq = tid & 3;
    int nglob = n0 + brow;
    const float* wrow = (nglob < G4) ? (wihf + (size_t)nglob * EE)
                                     : (wihb + (size_t)(nglob - G4) * EE);

    {
        uint4 aReg = *(const uint4*)(d_xh + (size_t)(m0 + arow) * 128 + apart * 4);
        float4 bReg = *(const float4*)(wrow + bq * 4);
        uint* dst = As2[0] + arow * 12 + apart * 4;
        dst[0] = aReg.x; dst[1] = aReg.y; dst[2] = aReg.z; dst[3] = aReg.w;
        uint* db = Bs2[0] + brow * 12 + bq * 2;
        db[0] = pkbf(bReg.x, bReg.y);
        db[1] = pkbf(bReg.z, bReg.w);
    }
    __syncthreads();

    for (int it = 0; it < 16; ++it) {
        int p = it & 1;

        uint afr[2][4], bfr[4][2];
        #pragma unroll
        for (int mi = 0; mi < 2; ++mi) {
            int mb = wm * 32 + mi * 16;
            const uint* ap = As2[p] + (mb + gid) * 12 + ctid;
            afr[mi][0] = ap[0];
            afr[mi][1] = ap[8 * 12];
            afr[mi][2] = ap[4];
            afr[mi][3] = ap[8 * 12 + 4];
        }
        #pragma unroll
        for (int ni = 0; ni < 4; ++ni) {
            int nb = wn * 32 + ni * 8;
            const uint* bp = Bs2[p] + (nb + gid) * 12 + ctid;
            bfr[ni][0] = bp[0];
            bfr[ni][1] = bp[4];
        }

        uint4 aReg;
        float4 bReg;
        if (it + 1 < 16) {
            int k0 = (it + 1) * 16;
            aReg = *(const uint4*)(d_xh + (size_t)(m0 + arow) * 128 + (k0 >> 1) + apart * 4);
            bReg = *(const float4*)(wrow + k0 + bq * 4);
        }

        #pragma unroll
        for (int mi = 0; mi < 2; ++mi)
            #pragma unroll
            for (int ni = 0; ni < 4; ++ni)
                MMA_BF16(acc[mi][ni], afr[mi], bfr[ni][0], bfr[ni][1]);

        if (it + 1 < 16) {
            uint* dst = As2[p ^ 1] + arow * 12 + apart * 4;
            dst[0] = aReg.x; dst[1] = aReg.y; dst[2] = aReg.z; dst[3] = aReg.w;
            uint* db = Bs2[p ^ 1] + brow * 12 + bq * 2;
            db[0] = pkbf(bReg.x, bReg.y);
            db[1] = pkbf(bReg.z, bReg.w);
        }
        __syncthreads();
    }

    // epilogue phase 1: bias + batch-pair pack -> smem staging
    #pragma unroll
    for (int mi = 0; mi < 2; ++mi)
        #pragma unroll
        for (int ni = 0; ni < 4; ++ni)
            #pragma unroll
            for (int r = 0; r < 4; ++r) {
                int n_local = wn * 32 + ni * 8 + 2 * ctid + (r & 1);
                int n = n0 + n_local;
                int dir = (n >= G4) ? 1 : 0;
                int rr = n - dir * G4;
                float val = acc[mi][ni][r] + (dir ? bbias[rr] : bf[rr]);
                float pv = __shfl_xor_sync(~0u, val, 4);   // partner batch b+1
                if ((gid & 1) == 0) {
                    int off = wm * 32 + mi * 16 + gid + (r >> 1) * 8;   // 0..127
                    int tl = off >> 6, bp = (off & 63) >> 1;
                    stage[n_local * 68 + tl * 32 + bp] = pkbf(val, pv);
                }
            }
    __syncthreads();

    // epilogue phase 2: coalesced STG.128 writeback
    {
        int t0 = m0 >> 6;
        int row = tid >> 2, ch = tid & 3;
        int n = n0 + row;
        int dir = (n >= G4) ? 1 : 0;
        int rr = n - dir * G4;
        #pragma unroll
        for (int j = 0; j < 4; ++j) {
            int off = ch * 16 + j * 4;          // 0..63 within row
            int tl = off >> 5, bp = off & 31;
            uint4 v = *(const uint4*)&stage[row * 68 + off];
            *(uint4*)&d_Gh[((size_t)dir * TT * G4 + (size_t)(t0 + tl) * G4 + rr) * 32 + bp] = v;
        }
    }
}

// ---------------- K3: persistent BiLSTM, bf16 tensor-core recurrence (R9) ----------------
__global__ void __launch_bounds__(128, 1) k3_lstm(
    const float* __restrict__ whhf, const float* __restrict__ whhb,
    const int* __restrict__ seq_len)
{
    extern __shared__ uint hsh2[];            // [104][72] bf16x2 (k-pair, n) 29952 B

    int tid = threadIdx.x;
    int dir = blockIdx.x / NBD;
    int sl  = blockIdx.x % NBD;
    int j0  = sl * HSL;
    const float* whh = dir ? whhb : whhf;

    int wid = tid >> 5, lane = tid & 31;
    int gid = lane >> 2, ctid = lane & 3;
    int u   = gid & 3;            // local hidden unit 0..3
    int q1  = gid >> 2;           // 0: rows {i,g}; 1: rows {f,o}
    int bnw = wid * 16;           // warp batch base
    int b0  = bnw + q1 * 8 + 2 * ctid;   // this thread's batch pair (b0, b0+1)

    // persistent bf16 A fragments (k16 tiles; zero-pad k>=200)
    uint aw[KT3][4];
    {
        int rowA = q1 * HH + j0 + u;
        int rowB = (q1 + 2) * HH + j0 + u;
        #pragma unroll
        for (int kt = 0; kt < KT3; ++kt) {
            int kA = kt * 16 + 2 * ctid;
            int kC = kA + 8;
            float a0 = whh[(size_t)rowA * HH + kA];
            float a1 = whh[(size_t)rowA * HH + kA + 1];
            float b0v = whh[(size_t)rowB * HH + kA];
            float b1v = whh[(size_t)rowB * HH + kA + 1];
            float a2 = (kC < HH) ? whh[(size_t)rowA * HH + kC] : 0.f;
            float a3 = (kC + 1 < HH) ? whh[(size_t)rowA * HH + kC + 1] : 0.f;
            float b2v = (kC < HH) ? whh[(size_t)rowB * HH + kC] : 0.f;
            float b3v = (kC + 1 < HH) ? whh[(size_t)rowB * HH + kC + 1] : 0.f;
            aw[kt][0] = pkbf(a0, a1);
            aw[kt][1] = pkbf(b0v, b1v);
            aw[kt][2] = pkbf(a2, a3);
            aw[kt][3] = pkbf(b2v, b3v);
        }
    }

    for (int i = tid; i < 4 * 72; i += 128) hsh2[100 * 72 + i] = 0u;

    int len0 = seq_len[b0], len1 = seq_len[b0 + 1];
    float c0 = 0.f, c1 = 0.f, hp0 = 0.f, hp1 = 0.f;
    uint pk = 0u;

    uint* hbase = d_hallh + (size_t)dir * HDIR;
    unsigned* flg = &d_flagsp[dir][0][0];

    int ls2 = tid >> 1, lhalf = tid & 1;
    int lslice = ls2 + (ls2 >= sl ? 1 : 0);
    bool loader = (tid < 2 * (NBD - 1));

    int goff[4];
    #pragma unroll
    for (int q = 0; q < 4; ++q)
        goff[q] = (q * HH + j0 + u) * 32 + (b0 >> 1);

    const uint* Gd = d_Gh + (size_t)dir * TT * G4 * 32;

    uint xg[4];
    {
        int t0 = dir ? (TT - 1) : 0;
        const uint* Gt = Gd + (size_t)t0 * G4 * 32;
        #pragma unroll
        for (int q = 0; q < 4; ++q) xg[q] = __ldcg(Gt + goff[q]);
    }

    for (int st = 0; st < TT; ++st) {
        int t = dir ? (TT - 1 - st) : st;
        int rs = dir ? (t + 1) : t;
        int ws = dir ? t : (t + 1);

        {
            uint ppk = __shfl_xor_sync(~0u, pk, 4);
            if ((u & 1) == 0) {
                uint olo = __byte_perm(pk, ppk, 0x5410);
                uint ohi = __byte_perm(pk, ppk, 0x7632);
                *(uint2*)&hsh2[(2 * sl + (u >> 1)) * 72 + b0] = make_uint2(olo, ohi);
            }
        }

        if (loader) {
            unsigned v;
            const unsigned* fp = flg + lslice * 32;
            do {
                asm volatile("ld.acquire.gpu.u32 %0, [%1];" : "=r"(v) : "l"(fp));
            } while (v < (unsigned)st);
            const uint4* src = (const uint4*)(hbase + (size_t)rs * HSLOT + lslice * 128);
            int r0 = 2 * lslice;
            #pragma unroll
            for (int g = 0; g < 4; ++g) {
                int co = lhalf * 4 + g;
                int base = co * 8;
                uint4 A0 = __ldcg(src + 0 * 8 + co);
                uint4 A1 = __ldcg(src + 1 * 8 + co);
                uint4 A2 = __ldcg(src + 2 * 8 + co);
                uint4 A3 = __ldcg(src + 3 * 8 + co);
                uint4 o;
                o.x = __byte_perm(A0.x, A1.x, 0x5410);
                o.y = __byte_perm(A0.x, A1.x, 0x7632);
                o.z = __byte_perm(A0.y, A1.y, 0x5410);
                o.w = __byte_perm(A0.y, A1.y, 0x7632);
                *(uint4*)&hsh2[r0 * 72 + base] = o;
                o.x = __byte_perm(A0.z, A1.z, 0x5410);
                o.y = __byte_perm(A0.z, A1.z, 0x7632);
                o.z = __byte_perm(A0.w, A1.w, 0x5410);
                o.w = __byte_perm(A0.w, A1.w, 0x7632);
                *(uint4*)&hsh2[r0 * 72 + base + 4] = o;
                o.x = __byte_perm(A2.x, A3.x, 0x5410);
                o.y = __byte_perm(A2.x, A3.x, 0x7632);
                o.z = __byte_perm(A2.y, A3.y, 0x5410);
                o.w = __byte_perm(A2.y, A3.y, 0x7632);
                *(uint4*)&hsh2[(r0 + 1) * 72 + base] = o;
                o.x = __byte_perm(A2.z, A3.z, 0x5410);
                o.y = __byte_perm(A2.z, A3.z, 0x7632);
                o.z = __byte_perm(A2.w, A3.w, 0x5410);
                o.w = __byte_perm(A2.w, A3.w, 0x7632);
                *(uint4*)&hsh2[(r0 + 1) * 72 + base + 4] = o;
            }
        }
        __syncthreads();

        float acc0[4] = {0.f, 0.f, 0.f, 0.f};
        float acc1[4] = {0.f, 0.f, 0.f, 0.f};
        #pragma unroll
        for (int kt = 0; kt < KT3; ++kt) {
            const uint* hk = hsh2 + (kt * 8 + ctid) * 72;
            uint b00 = hk[bnw + gid];
            uint b01 = hk[4 * 72 + bnw + gid];
            uint b10 = hk[bnw + 8 + gid];
            uint b11 = hk[4 * 72 + bnw + 8 + gid];
            MMA_BF16(acc0, aw[kt], b00, b01);
            MMA_BF16(acc1, aw[kt], b10, b11);
        }

        float s0 = q1 ? acc0[0] : acc1[0];
        float s1 = q1 ? acc0[1] : acc1[1];
        float s2 = q1 ? acc0[2] : acc1[2];
        float s3 = q1 ? acc0[3] : acc1[3];
        float o0 = __shfl_xor_sync(~0u, s0, 16);
        float o1 = __shfl_xor_sync(~0u, s1, 16);
        float o2 = __shfl_xor_sync(~0u, s2, 16);
        float o3 = __shfl_xor_sync(~0u, s3, 16);
        float m0 = q1 ? acc1[0] : acc0[0];
        float m1 = q1 ? acc1[1] : acc0[1];
        float m2 = q1 ? acc1[2] : acc0[2];
        float m3 = q1 ? acc1[3] : acc0[3];
        float gi0 = q1 ? o0 : m0,  gf0 = q1 ? m0 : o0;
        float gg0 = q1 ? o2 : m2,  go0 = q1 ? m2 : o2;
        float gi1 = q1 ? o1 : m1,  gf1 = q1 ? m1 : o1;
        float gg1 = q1 ? o3 : m3,  go1 = q1 ? m3 : o3;

        {
            float cn = sigf(gf0 + bflo(xg[1])) * c0
                     + sigf(gi0 + bflo(xg[0])) * tanhfast(gg0 + bflo(xg[2]));
            float hn = sigf(go0 + bflo(xg[3])) * tanhfast(cn);
            bool valid = (t < len0);
            hp0 = valid ? hn : hp0;
            c0  = valid ? cn : c0;
        }
        {
            float cn = sigf(gf1 + bfhi(xg[1])) * c1
                     + sigf(gi1 + bfhi(xg[0])) * tanhfast(gg1 + bfhi(xg[2]));
            float hn = sigf(go1 + bfhi(xg[3])) * tanhfast(cn);
            bool valid = (t < len1);
            hp1 = valid ? hn : hp1;
            c1  = valid ? cn : c1;
        }

        pk = pkbf(hp0, hp1);
        __stcg(hbase + (size_t)ws * HSLOT + sl * 128 + u * 32 + (b0 >> 1), pk);

        __syncthreads();
        if (tid == 0) {
            asm volatile("fence.acq_rel.gpu;" ::: "memory");
            asm volatile("st.relaxed.gpu.u32 [%0], %1;"
                         :: "l"(flg + sl * 32), "r"((unsigned)(st + 1)) : "memory");
        }

        if (st + 1 < TT) {
            int tn = dir ? (TT - 2 - st) : (st + 1);
            const uint* Gt = Gd + (size_t)tn * G4 * 32;
            #pragma unroll
            for (int q = 0; q < 4; ++q) xg[q] = __ldcg(Gt + goff[q]);
        }
    }
}

// ---------------- K4: FC + log_softmax, f32-staged h (block = 16 tokens) ----------------
#define K4SMEM ((CC * 402 + 16 * 400) * 4)
__global__ void __launch_bounds__(128) k4_fc(
    const float* __restrict__ fcw, const float* __restrict__ fcb)
{
    extern __shared__ float k4s[];
    float* wsh = k4s;                  // CC * 402
    float* hsf = k4s + CC * 402;       // [16 tokens][400 features] f32
    __shared__ float fbsh[CC];
    int tid = threadIdx.x;
    int bid = blockIdx.x;
    int t = bid >> 2, bg = bid & 3, b0 = bg * 16;

    for (int i = tid; i < CC * 400; i += 128) {
        int c = i / 400, j = i % 400;
        wsh[c * 402 + j] = fcw[i];
    }
    if (tid < CC) fbsh[tid] = fcb[tid];

    for (int c = tid; c < 1600; c += 128) {
        int row = c >> 2, part = c & 3;
        int dirr = (row >= HH) ? 1 : 0;
        int jj = row - dirr * HH;
        size_t slot = dirr ? (size_t)t : (size_t)(t + 1);
        size_t addr = (size_t)dirr * HDIR + slot * HSLOT
                    + (jj >> 2) * 128 + (jj & 3) * 32 + (b0 >> 1) + part * 2;
        uint2 v = *(const uint2*)&d_hallh[addr];
        int tokbase = part * 4;
        hsf[(tokbase + 0) * 400 + row] = bflo(v.x);
        hsf[(tokbase + 1) * 400 + row] = bfhi(v.x);
        hsf[(tokbase + 2) * 400 + row] = bflo(v.y);
        hsf[(tokbase + 3) * 400 + row] = bfhi(v.y);
    }
    __syncthreads();

    int w = tid >> 5, lane = tid & 31;
    #pragma unroll
    for (int tk = 0; tk < 4; ++tk) {
        int bloc = w * 4 + tk;
        const float* hrow = hsf + bloc * 400;
        float acc = -1e30f;
        if (lane < CC) {
            acc = fbsh[lane];
            const float* wr = wsh + lane * 402;
            #pragma unroll 4
            for (int j = 0; j < 400; j += 2) {
                float2 hv = *(const float2*)&hrow[j];
                float2 wv = *(const float2*)&wr[j];
                acc += hv.x * wv.x + hv.y * wv.y;
            }
        }
        float m = acc;
        #pragma unroll
        for (int o = 16; o; o >>= 1) m = fmaxf(m, __shfl_xor_sync(~0u, m, o));
        float e = (lane < CC) ? __expf(acc - m) : 0.f;
        #pragma unroll
        for (int o = 16; o; o >>= 1) e += __shfl_xor_sync(~0u, e, o);
        float lse = m + __logf(e);
        if (lane < CC) {
            int b = b0 + bloc;
            d_logits[((size_t)b * TT + t) * CC + lane] = acc - lse;
        }
    }
}

// ---------------- K5: CRF NLL, exp-factored transition matrix ----------------
__global__ void __launch_bounds__(32) k5_crf(
    const int* __restrict__ seq_len, const int* __restrict__ target,
    const float* __restrict__ trans, const float* __restrict__ start,
    const float* __restrict__ endsc)
{
    int b = blockIdx.x;
    int lane = threadIdx.x;
    int c = (lane < CC) ? lane : 0;
    int len = seq_len[b];
    const float* L = d_logits + (size_t)b * TT * CC;
    const int* tg = target + (size_t)b * TT;

    // E[i] = exp(trans[i][c]) — precomputed once, 20 regs/lane
    float E[CC];
    #pragma unroll
    for (int i = 0; i < CC; ++i)
        E[i] = (lane < CC) ? __expf(trans[i * CC + c]) : 0.f;

    float alpha = (lane < CC) ? (start[c] + L[c]) : -1e30f;
    float emit = (lane < CC && len > 1) ? L[CC + c] : 0.f;   // prefetch t=1

    for (int t = 1; t < len; ++t) {
        // m = max_i alpha_i via butterfly (lanes>=20 hold -1e30)
        float m = alpha;
        #pragma unroll
        for (int o = 16; o; o >>= 1) m = fmaxf(m, __shfl_xor_sync(~0u, m, o));
        float p = __expf(alpha - m);            // 1 expf instead of 20
        float s = 0.f;
        #pragma unroll
        for (int i = 0; i < CC; ++i)
            s += __shfl_sync(~0u, p, i) * E[i];
        float na = m + __logf(s) + emit;
        // prefetch next emit off the serial chain
        if (t + 1 < len) emit = (lane < CC) ? L[(t + 1) * CC + c] : 0.f;
        alpha = (lane < CC) ? na : -1e30f;
    }

    // logZ = lse(alpha + end)
    float v = (lane < CC) ? (alpha + endsc[c]) : -1e30f;
    float m = v;
    #pragma unroll
    for (int o = 16; o; o >>= 1) m = fmaxf(m, __shfl_xor_sync(~0u, m, o));
    float s = __expf(v - m);
    if (lane >= CC) s = 0.f;
    #pragma unroll
    for (int o = 16; o; o >>= 1) s += __shfl_xor_sync(~0u, s, o);
    float logZ = m + __logf(s);

    // gold score
    float es = 0.f;
    for (int t = lane; t < len; t += 32) es += L[t * CC + tg[t]];
    float ts = 0.f;
    for (int t = lane; t < len - 1; t += 32) ts += trans[tg[t] * CC + tg[t + 1]];
    float g = es + ts;
    #pragma unroll
    for (int o = 16; o; o >>= 1) g += __shfl_xor_sync(~0u, g, o);
    if (lane == 0) {
        float gold = g + start[tg[0]] + endsc[tg[len - 1]];
        d_loss[b] = logZ - gold;
    }
}

// ---------------- K6: mean reduce ----------------
__global__ void __launch_bounds__(64) k6_mean(float* out) {
    __shared__ float sh[64];
    int tid = threadIdx.x;
    sh[tid] = d_loss[tid];
    __syncthreads();
    for (int o = 32; o; o >>= 1) {
        if (tid < o) sh[tid] += sh[tid + o];
        __syncthreads();
    }
    if (tid == 0) out[0] = sh[0] * (1.f / BB);
}

// ---------------- launch ----------------
extern "C" void kernel_launch(void* const* d_in, const int* in_sizes, int n_in,
                              void* d_out, int out_size) {
    const int*   words   = (const int*)d_in[0];
    const int*   seq_len = (const int*)d_in[1];
    const int*   target  = (const int*)d_in[2];
    const float* embed   = (const float*)d_in[3];
    const float* gamma   = (const float*)d_in[4];
    const float* beta    = (const float*)d_in[5];
    const float* wihf    = (const float*)d_in[6];
    const float* whhf    = (const float*)d_in[7];
    const float* bf      = (const float*)d_in[8];
    const float* wihb    = (const float*)d_in[9];
    const float* whhb    = (const float*)d_in[10];
    const float* bb      = (const float*)d_in[11];
    const float* fcw     = (const float*)d_in[12];
    const float* fcb     = (const float*)d_in[13];
    const float* trans   = (const float*)d_in[14];
    const float* startsc = (const float*)d_in[15];
    const float* endsc   = (const float*)d_in[16];
    float* out = (float*)d_out;

    size_t hsmem = (size_t)(104 * 72) * sizeof(uint);   // 29952 B
    cudaFuncSetAttribute(k3_lstm, cudaFuncAttributeMaxDynamicSharedMemorySize,
                         (int)hsmem);
    cudaFuncSetAttribute(k4_fc, cudaFuncAttributeMaxDynamicSharedMemorySize,
                         K4SMEM);

    k1_embed_ln<<<TT * BB / 8, 256>>>(words, embed, gamma, beta);
    {
        dim3 g(2 * G4 / 64, TT * BB / 128);   // 25 x 256
        k2_gemm<<<g, 256>>>(wihf, wihb, bf, bb);
    }
    k3_lstm<<<2 * NBD, 128, hsmem>>>(whhf, whhb, seq_len);
    k4_fc<<<TT * 4, 128, K4SMEM>>>(fcw, fcb);
    k5_crf<<<BB, 32>>>(seq_len, target, trans, startsc, endsc);
    k6_mean<<<1, 64>>>(out);
}

// round 15
// speedup vs baseline: 1.1674x; 1.0448x over previous
#include <cuda_runtime.h>
#include <cuda_bf16.h>
#include <math.h>

#define TT 512
#define BB 64
#define EE 256
#define HH 200
#define G4 800
#define CC 20
#define NBD 50   // blocks per direction in LSTM kernel
#define HSL 4    // h-units per block (HH / NBD)
#define KT3 13   // k16-tiles covering HH=200 (pad to 208)

typedef unsigned int uint;

// ---------------- device scratch (no allocations allowed) ----------------
__device__ uint  d_xh[TT * BB * (EE / 2)];        // LN'd embeddings bf16x2
__device__ uint  d_Gh[2 * TT * G4 * 32];          // gates_x bf16x2 (batch pairs)
__device__ uint  d_hallh[2 * (TT + 1) * NBD * 128]; // h history bf16x2 [dir][slot][sl][u*32+bp]
__device__ float d_logits[BB * TT * CC];          // log_softmax outputs [b][t][c]
__device__ float d_loss[BB];
__device__ unsigned d_flagsp[2][NBD][32];         // flags spread 128B apart

#define HSLOT 6400           // uints per history slot (NBD*128)
#define HDIR  ((TT + 1) * HSLOT)

__device__ __forceinline__ uint pkbf(float lo, float hi) {
    uint r;
    asm("cvt.rn.bf16x2.f32 %0, %1, %2;" : "=r"(r) : "f"(hi), "f"(lo));
    return r;
}
__device__ __forceinline__ float bflo(uint v) { return __uint_as_float(v << 16); }
__device__ __forceinline__ float bfhi(uint v) { return __uint_as_float(v & 0xffff0000u); }
__device__ __forceinline__ float sigf(float x)  { return 1.f / (1.f + __expf(-x)); }
__device__ __forceinline__ float tanhfast(float x) { return 1.f - 2.f / (__expf(2.f * x) + 1.f); }

#define MMA_BF16(ACC, A, B0, B1)                                           \
    asm volatile(                                                          \
        "mma.sync.aligned.m16n8k16.row.col.f32.bf16.bf16.f32 "             \
        "{%0,%1,%2,%3}, {%4,%5,%6,%7}, {%8,%9}, {%0,%1,%2,%3};"            \
        : "+f"((ACC)[0]), "+f"((ACC)[1]), "+f"((ACC)[2]), "+f"((ACC)[3])   \
        : "r"((A)[0]), "r"((A)[1]), "r"((A)[2]), "r"((A)[3]),              \
          "r"(B0), "r"(B1))

// ---------------- K1: embedding + LayerNorm -> bf16x2; block 0 also inits ----------------
__global__ void __launch_bounds__(256) k1_embed_ln(
    const int* __restrict__ words, const float* __restrict__ embed,
    const float* __restrict__ gamma, const float* __restrict__ beta)
{
    if (blockIdx.x == 0) {
        int t0 = threadIdx.x;
        for (int i = t0; i < HSLOT; i += 256) {
            d_hallh[i] = 0u;                              // dir0, slot 0
            d_hallh[HDIR + (size_t)TT * HSLOT + i] = 0u;  // dir1, slot TT
        }
        for (int i = t0; i < 2 * NBD * 32; i += 256) ((unsigned*)d_flagsp)[i] = 0u;
    }

    int wid = threadIdx.x >> 5, lane = threadIdx.x & 31;
    int tok = blockIdx.x * 8 + wid;          // tok = t*64 + b
    int t = tok >> 6, b = tok & 63;
    int word = words[b * TT + t];
    const float4* src = (const float4*)(embed + (size_t)word * EE);
    float4 v0 = src[lane * 2], v1 = src[lane * 2 + 1];
    float s = v0.x + v0.y + v0.z + v0.w + v1.x + v1.y + v1.z + v1.w;
    float q = v0.x*v0.x + v0.y*v0.y + v0.z*v0.z + v0.w*v0.w
            + v1.x*v1.x + v1.y*v1.y + v1.z*v1.z + v1.w*v1.w;
    #pragma unroll
    for (int o = 16; o; o >>= 1) {
        s += __shfl_xor_sync(~0u, s, o);
        q += __shfl_xor_sync(~0u, q, o);
    }
    float mu  = s * (1.f / EE);
    float var = q * (1.f / EE) - mu * mu;
    float rs  = rsqrtf(var + 1e-5f);
    const float4* g4 = (const float4*)gamma;
    const float4* bt4 = (const float4*)beta;
    float4 ga = g4[lane*2], gb = g4[lane*2+1];
    float4 ba = bt4[lane*2], bb = bt4[lane*2+1];
    float o0x = (v0.x-mu)*rs*ga.x + ba.x,  o0y = (v0.y-mu)*rs*ga.y + ba.y;
    float o0z = (v0.z-mu)*rs*ga.z + ba.z,  o0w = (v0.w-mu)*rs*ga.w + ba.w;
    float o1x = (v1.x-mu)*rs*gb.x + bb.x,  o1y = (v1.y-mu)*rs*gb.y + bb.y;
    float o1z = (v1.z-mu)*rs*gb.z + bb.z,  o1w = (v1.w-mu)*rs*gb.w + bb.w;
    uint4 pk;
    pk.x = pkbf(o0x, o0y);  pk.y = pkbf(o0z, o0w);
    pk.z = pkbf(o1x, o1y);  pk.w = pkbf(o1z, o1w);
    *(uint4*)(d_xh + (size_t)tok * 128 + lane * 4) = pk;
}

// ---------------- K2: bf16 TC GEMM, double-buffered + staged coalesced epilogue ----------------
__global__ void __launch_bounds__(256) k2_gemm(
    const float* __restrict__ wihf, const float* __restrict__ wihb,
    const float* __restrict__ bf,   const float* __restrict__ bbias)
{
    __shared__ uint As2[2][128 * 12];   // [buf][m][k/2] bf16x2
    __shared__ uint Bs2[2][64 * 12];
    __shared__ uint stage[64 * 68];     // epilogue staging

    int tid = threadIdx.x;
    int m0 = blockIdx.y * 128, n0 = blockIdx.x * 64;
    int wid = tid >> 5, lane = tid & 31;
    int wm = wid & 3, wn = wid >> 2;            // warp grid 4 x 2
    int gid = lane >> 2, ctid = lane & 3;

    float acc[2][4][4];
    #pragma unroll
    for (int mi = 0; mi < 2; ++mi)
        #pragma unroll
        for (int ni = 0; ni < 4; ++ni)
            #pragma unroll
            for (int r = 0; r < 4; ++r) acc[mi][ni][r] = 0.f;

    int arow = tid >> 1, apart = tid & 1;
    int brow = tid >> 2, bq = tid & 3;
    int nglob = n0 + brow;
    const float* wrow = (nglob < G4) ? (wihf + (size_t)nglob * EE)
                                     : (wihb + (size_t)(nglob - G4) * EE);

    {
        uint4 aReg = *(const uint4*)(d_xh + (size_t)(m0 + arow) * 128 + apart * 4);
        float4 bReg = *(const float4*)(wrow + bq * 4);
        uint* dst = As2[0] + arow * 12 + apart * 4;
        dst[0] = aReg.x; dst[1] = aReg.y; dst[2] = aReg.z; dst[3] = aReg.w;
        uint* db = Bs2[0] + brow * 12 + bq * 2;
        db[0] = pkbf(bReg.x, bReg.y);
        db[1] = pkbf(bReg.z, bReg.w);
    }
    __syncthreads();

    for (int it = 0; it < 16; ++it) {
        int p = it & 1;

        uint afr[2][4], bfr[4][2];
        #pragma unroll
        for (int mi = 0; mi < 2; ++mi) {
            int mb = wm * 32 + mi * 16;
            const uint* ap = As2[p] + (mb + gid) * 12 + ctid;
            afr[mi][0] = ap[0];
            afr[mi][1] = ap[8 * 12];
            afr[mi][2] = ap[4];
            afr[mi][3] = ap[8 * 12 + 4];
        }
        #pragma unroll
        for (int ni = 0; ni < 4; ++ni) {
            int nb = wn * 32 + ni * 8;
            const uint* bp = Bs2[p] + (nb + gid) * 12 + ctid;
            bfr[ni][0] = bp[0];
            bfr[ni][1] = bp[4];
        }

        uint4 aReg;
        float4 bReg;
        if (it + 1 < 16) {
            int k0 = (it + 1) * 16;
            aReg = *(const uint4*)(d_xh + (size_t)(m0 + arow) * 128 + (k0 >> 1) + apart * 4);
            bReg = *(const float4*)(wrow + k0 + bq * 4);
        }

        #pragma unroll
        for (int mi = 0; mi < 2; ++mi)
            #pragma unroll
            for (int ni = 0; ni < 4; ++ni)
                MMA_BF16(acc[mi][ni], afr[mi], bfr[ni][0], bfr[ni][1]);

        if (it + 1 < 16) {
            uint* dst = As2[p ^ 1] + arow * 12 + apart * 4;
            dst[0] = aReg.x; dst[1] = aReg.y; dst[2] = aReg.z; dst[3] = aReg.w;
            uint* db = Bs2[p ^ 1] + brow * 12 + bq * 2;
            db[0] = pkbf(bReg.x, bReg.y);
            db[1] = pkbf(bReg.z, bReg.w);
        }
        __syncthreads();
    }

    #pragma unroll
    for (int mi = 0; mi < 2; ++mi)
        #pragma unroll
        for (int ni = 0; ni < 4; ++ni)
            #pragma unroll
            for (int r = 0; r < 4; ++r) {
                int n_local = wn * 32 + ni * 8 + 2 * ctid + (r & 1);
                int n = n0 + n_local;
                int dir = (n >= G4) ? 1 : 0;
                int rr = n - dir * G4;
                float val = acc[mi][ni][r] + (dir ? bbias[rr] : bf[rr]);
                float pv = __shfl_xor_sync(~0u, val, 4);   // partner batch b+1
                if ((gid & 1) == 0) {
                    int off = wm * 32 + mi * 16 + gid + (r >> 1) * 8;   // 0..127
                    int tl = off >> 6, bp = (off & 63) >> 1;
                    stage[n_local * 68 + tl * 32 + bp] = pkbf(val, pv);
                }
            }
    __syncthreads();

    {
        int t0 = m0 >> 6;
        int row = tid >> 2, ch = tid & 3;
        int n = n0 + row;
        int dir = (n >= G4) ? 1 : 0;
        int rr = n - dir * G4;
        #pragma unroll
        for (int j = 0; j < 4; ++j) {
            int off = ch * 16 + j * 4;
            int tl = off >> 5, bp = off & 31;
            uint4 v = *(const uint4*)&stage[row * 68 + off];
            *(uint4*)&d_Gh[((size_t)dir * TT * G4 + (size_t)(t0 + tl) * G4 + rr) * 32 + bp] = v;
        }
    }
}

// ---------------- K3: persistent BiLSTM, bf16 tensor-core recurrence (R9) ----------------
__global__ void __launch_bounds__(128, 1) k3_lstm(
    const float* __restrict__ whhf, const float* __restrict__ whhb,
    const int* __restrict__ seq_len)
{
    extern __shared__ uint hsh2[];            // [104][72] bf16x2 (k-pair, n) 29952 B

    int tid = threadIdx.x;
    int dir = blockIdx.x / NBD;
    int sl  = blockIdx.x % NBD;
    int j0  = sl * HSL;
    const float* whh = dir ? whhb : whhf;

    int wid = tid >> 5, lane = tid & 31;
    int gid = lane >> 2, ctid = lane & 3;
    int u   = gid & 3;
    int q1  = gid >> 2;
    int bnw = wid * 16;
    int b0  = bnw + q1 * 8 + 2 * ctid;

    uint aw[KT3][4];
    {
        int rowA = q1 * HH + j0 + u;
        int rowB = (q1 + 2) * HH + j0 + u;
        #pragma unroll
        for (int kt = 0; kt < KT3; ++kt) {
            int kA = kt * 16 + 2 * ctid;
            int kC = kA + 8;
            float a0 = whh[(size_t)rowA * HH + kA];
            float a1 = whh[(size_t)rowA * HH + kA + 1];
            float b0v = whh[(size_t)rowB * HH + kA];
            float b1v = whh[(size_t)rowB * HH + kA + 1];
            float a2 = (kC < HH) ? whh[(size_t)rowA * HH + kC] : 0.f;
            float a3 = (kC + 1 < HH) ? whh[(size_t)rowA * HH + kC + 1] : 0.f;
            float b2v = (kC < HH) ? whh[(size_t)rowB * HH + kC] : 0.f;
            float b3v = (kC + 1 < HH) ? whh[(size_t)rowB * HH + kC + 1] : 0.f;
            aw[kt][0] = pkbf(a0, a1);
            aw[kt][1] = pkbf(b0v, b1v);
            aw[kt][2] = pkbf(a2, a3);
            aw[kt][3] = pkbf(b2v, b3v);
        }
    }

    for (int i = tid; i < 4 * 72; i += 128) hsh2[100 * 72 + i] = 0u;

    int len0 = seq_len[b0], len1 = seq_len[b0 + 1];
    float c0 = 0.f, c1 = 0.f, hp0 = 0.f, hp1 = 0.f;
    uint pk = 0u;

    uint* hbase = d_hallh + (size_t)dir * HDIR;
    unsigned* flg = &d_flagsp[dir][0][0];

    int ls2 = tid >> 1, lhalf = tid & 1;
    int lslice = ls2 + (ls2 >= sl ? 1 : 0);
    bool loader = (tid < 2 * (NBD - 1));

    int goff[4];
    #pragma unroll
    for (int q = 0; q < 4; ++q)
        goff[q] = (q * HH + j0 + u) * 32 + (b0 >> 1);

    const uint* Gd = d_Gh + (size_t)dir * TT * G4 * 32;

    uint xg[4];
    {
        int t0 = dir ? (TT - 1) : 0;
        const uint* Gt = Gd + (size_t)t0 * G4 * 32;
        #pragma unroll
        for (int q = 0; q < 4; ++q) xg[q] = __ldcg(Gt + goff[q]);
    }

    for (int st = 0; st < TT; ++st) {
        int t = dir ? (TT - 1 - st) : st;
        int rs = dir ? (t + 1) : t;
        int ws = dir ? t : (t + 1);

        {
            uint ppk = __shfl_xor_sync(~0u, pk, 4);
            if ((u & 1) == 0) {
                uint olo = __byte_perm(pk, ppk, 0x5410);
                uint ohi = __byte_perm(pk, ppk, 0x7632);
                *(uint2*)&hsh2[(2 * sl + (u >> 1)) * 72 + b0] = make_uint2(olo, ohi);
            }
        }

        if (loader) {
            unsigned v;
            const unsigned* fp = flg + lslice * 32;
            do {
                asm volatile("ld.acquire.gpu.u32 %0, [%1];" : "=r"(v) : "l"(fp));
            } while (v < (unsigned)st);
            const uint4* src = (const uint4*)(hbase + (size_t)rs * HSLOT + lslice * 128);
            int r0 = 2 * lslice;
            #pragma unroll
            for (int g = 0; g < 4; ++g) {
                int co = lhalf * 4 + g;
                int base = co * 8;
                uint4 A0 = __ldcg(src + 0 * 8 + co);
                uint4 A1 = __ldcg(src + 1 * 8 + co);
                uint4 A2 = __ldcg(src + 2 * 8 + co);
                uint4 A3 = __ldcg(src + 3 * 8 + co);
                uint4 o;
                o.x = __byte_perm(A0.x, A1.x, 0x5410);
                o.y = __byte_perm(A0.x, A1.x, 0x7632);
                o.z = __byte_perm(A0.y, A1.y, 0x5410);
                o.w = __byte_perm(A0.y, A1.y, 0x7632);
                *(uint4*)&hsh2[r0 * 72 + base] = o;
                o.x = __byte_perm(A0.z, A1.z, 0x5410);
                o.y = __byte_perm(A0.z, A1.z, 0x7632);
                o.z = __byte_perm(A0.w, A1.w, 0x5410);
                o.w = __byte_perm(A0.w, A1.w, 0x7632);
                *(uint4*)&hsh2[r0 * 72 + base + 4] = o;
                o.x = __byte_perm(A2.x, A3.x, 0x5410);
                o.y = __byte_perm(A2.x, A3.x, 0x7632);
                o.z = __byte_perm(A2.y, A3.y, 0x5410);
                o.w = __byte_perm(A2.y, A3.y, 0x7632);
                *(uint4*)&hsh2[(r0 + 1) * 72 + base] = o;
                o.x = __byte_perm(A2.z, A3.z, 0x5410);
                o.y = __byte_perm(A2.z, A3.z, 0x7632);
                o.z = __byte_perm(A2.w, A3.w, 0x5410);
                o.w = __byte_perm(A2.w, A3.w, 0x7632);
                *(uint4*)&hsh2[(r0 + 1) * 72 + base + 4] = o;
            }
        }
        __syncthreads();

        float acc0[4] = {0.f, 0.f, 0.f, 0.f};
        float acc1[4] = {0.f, 0.f, 0.f, 0.f};
        #pragma unroll
        for (int kt = 0; kt < KT3; ++kt) {
            const uint* hk = hsh2 + (kt * 8 + ctid) * 72;
            uint b00 = hk[bnw + gid];
            uint b01 = hk[4 * 72 + bnw + gid];
            uint b10 = hk[bnw + 8 + gid];
            uint b11 = hk[4 * 72 + bnw + 8 + gid];
            MMA_BF16(acc0, aw[kt], b00, b01);
            MMA_BF16(acc1, aw[kt], b10, b11);
        }

        float s0 = q1 ? acc0[0] : acc1[0];
        float s1 = q1 ? acc0[1] : acc1[1];
        float s2 = q1 ? acc0[2] : acc1[2];
        float s3 = q1 ? acc0[3] : acc1[3];
        float o0 = __shfl_xor_sync(~0u, s0, 16);
        float o1 = __shfl_xor_sync(~0u, s1, 16);
        float o2 = __shfl_xor_sync(~0u, s2, 16);
        float o3 = __shfl_xor_sync(~0u, s3, 16);
        float m0 = q1 ? acc1[0] : acc0[0];
        float m1 = q1 ? acc1[1] : acc0[1];
        float m2 = q1 ? acc1[2] : acc0[2];
        float m3 = q1 ? acc1[3] : acc0[3];
        float gi0 = q1 ? o0 : m0,  gf0 = q1 ? m0 : o0;
        float gg0 = q1 ? o2 : m2,  go0 = q1 ? m2 : o2;
        float gi1 = q1 ? o1 : m1,  gf1 = q1 ? m1 : o1;
        float gg1 = q1 ? o3 : m3,  go1 = q1 ? m3 : o3;

        {
            float cn = sigf(gf0 + bflo(xg[1])) * c0
                     + sigf(gi0 + bflo(xg[0])) * tanhfast(gg0 + bflo(xg[2]));
            float hn = sigf(go0 + bflo(xg[3])) * tanhfast(cn);
            bool valid = (t < len0);
            hp0 = valid ? hn : hp0;
            c0  = valid ? cn : c0;
        }
        {
            float cn = sigf(gf1 + bfhi(xg[1])) * c1
                     + sigf(gi1 + bfhi(xg[0])) * tanhfast(gg1 + bfhi(xg[2]));
            float hn = sigf(go1 + bfhi(xg[3])) * tanhfast(cn);
            bool valid = (t < len1);
            hp1 = valid ? hn : hp1;
            c1  = valid ? cn : c1;
        }

        pk = pkbf(hp0, hp1);
        __stcg(hbase + (size_t)ws * HSLOT + sl * 128 + u * 32 + (b0 >> 1), pk);

        __syncthreads();
        if (tid == 0) {
            asm volatile("fence.acq_rel.gpu;" ::: "memory");
            asm volatile("st.relaxed.gpu.u32 [%0], %1;"
                         :: "l"(flg + sl * 32), "r"((unsigned)(st + 1)) : "memory");
        }

        if (st + 1 < TT) {
            int tn = dir ? (TT - 2 - st) : (st + 1);
            const uint* Gt = Gd + (size_t)tn * G4 * 32;
            #pragma unroll
            for (int q = 0; q < 4; ++q) xg[q] = __ldcg(Gt + goff[q]);
        }
    }
}

// ---------------- K4: FC + log_softmax via bf16 tensor cores (block = one t, 64 tokens) ----------------
// A = h [64 tokens][400] bf16 pairs (stride 201), B = fc_w [24 classes][400] (rows 20-23 zero).
// 4 warps x 1 m16-tile x 3 n8-tiles x 25 k16-tiles. Quad-shfl log_softmax epilogue.
#define K4SMEM ((64 * 201 + 24 * 201) * 4)
__global__ void __launch_bounds__(128) k4_fc(
    const float* __restrict__ fcw, const float* __restrict__ fcb)
{
    extern __shared__ uint k4u[];
    uint* Ah = k4u;                 // [64][201]
    uint* Bsw = k4u + 64 * 201;     // [24][201]
    __shared__ float fbsh[24];

    int tid = threadIdx.x;
    int t = blockIdx.x;
    int wid = tid >> 5, lane = tid & 31;
    int gid = lane >> 2, ctid = lane & 3;

    // stage W_fc as bf16 pairs (rows 20..23 zero)
    for (int i = tid; i < 24 * 200; i += 128) {
        int c = i / 200, j = i % 200;
        uint v = 0u;
        if (c < CC) {
            float w0 = fcw[c * 400 + 2 * j];
            float w1 = fcw[c * 400 + 2 * j + 1];
            v = pkbf(w0, w1);
        }
        Bsw[c * 201 + j] = v;
    }
    if (tid < 24) fbsh[tid] = (tid < CC) ? fcb[tid] : 0.f;

    // stage h: feature-pairs per token via PRMT (h already bf16 — exact)
    for (int idx = tid; idx < 6400; idx += 128) {
        int j = idx >> 5, bp = idx & 31;             // j = feature pair, bp = batch pair
        int dirr = (j >= 100) ? 1 : 0;
        int jj = 2 * j - dirr * 2 * HH + 0;          // feature 2j local
        size_t base = (size_t)dirr * HDIR
                    + (size_t)(dirr ? t : (t + 1)) * HSLOT;
        uint U0 = d_hallh[base + (jj >> 2) * 128 + (jj & 3) * 32 + bp];
        int jk = jj + 1;
        uint U1 = d_hallh[base + (jk >> 2) * 128 + (jk & 3) * 32 + bp];
        Ah[(2 * bp) * 201 + j]     = __byte_perm(U0, U1, 0x5410);
        Ah[(2 * bp + 1) * 201 + j] = __byte_perm(U0, U1, 0x7632);
    }
    __syncthreads();

    // mma: tokens = wid*16 + gid (+8); 3 n-tiles of 8 classes; K = 400 (25 kt)
    float acc[3][4] = {{0,0,0,0},{0,0,0,0},{0,0,0,0}};
    int mb = wid * 16;
    #pragma unroll 5
    for (int kt = 0; kt < 25; ++kt) {
        uint afr[4];
        const uint* ap = Ah + (mb + gid) * 201 + kt * 8 + ctid;
        afr[0] = ap[0];
        afr[1] = ap[8 * 201];
        afr[2] = ap[4];
        afr[3] = ap[8 * 201 + 4];
        #pragma unroll
        for (int ni = 0; ni < 3; ++ni) {
            const uint* bp_ = Bsw + (ni * 8 + gid) * 201 + kt * 8 + ctid;
            MMA_BF16(acc[ni], afr, bp_[0], bp_[4]);
        }
    }

    // epilogue: per token-row, 6 classes/thread; quad shfl (xor 1,2) log_softmax
    #pragma unroll
    for (int rs = 0; rs < 2; ++rs) {
        int b = mb + gid + rs * 8;
        float v[6];
        float mx = -1e30f;
        #pragma unroll
        for (int ni = 0; ni < 3; ++ni) {
            #pragma unroll
            for (int k = 0; k < 2; ++k) {
                int cls = ni * 8 + 2 * ctid + k;
                float x = acc[ni][rs * 2 + k] + fbsh[cls];
                if (cls >= CC) x = -1e30f;
                v[ni * 2 + k] = x;
                mx = fmaxf(mx, x);
            }
        }
        mx = fmaxf(mx, __shfl_xor_sync(~0u, mx, 1));
        mx = fmaxf(mx, __shfl_xor_sync(~0u, mx, 2));
        float s = 0.f;
        #pragma unroll
        for (int k = 0; k < 6; ++k) s += __expf(v[k] - mx);
        s += __shfl_xor_sync(~0u, s, 1);
        s += __shfl_xor_sync(~0u, s, 2);
        float lse = mx + __logf(s);
        #pragma unroll
        for (int ni = 0; ni < 3; ++ni)
            #pragma unroll
            for (int k = 0; k < 2; ++k) {
                int cls = ni * 8 + 2 * ctid + k;
                if (cls < CC)
                    d_logits[((size_t)b * TT + t) * CC + cls] = v[ni * 2 + k] - lse;
            }
    }
}

// ---------------- K5: CRF NLL, exp-factored transition matrix ----------------
__global__ void __launch_bounds__(32) k5_crf(
    const int* __restrict__ seq_len, const int* __restrict__ target,
    const float* __restrict__ trans, const float* __restrict__ start,
    const float* __restrict__ endsc)
{
    int b = blockIdx.x;
    int lane = threadIdx.x;
    int c = (lane < CC) ? lane : 0;
    int len = seq_len[b];
    const float* L = d_logits + (size_t)b * TT * CC;
    const int* tg = target + (size_t)b * TT;

    float E[CC];
    #pragma unroll
    for (int i = 0; i < CC; ++i)
        E[i] = (lane < CC) ? __expf(trans[i * CC + c]) : 0.f;

    float alpha = (lane < CC) ? (start[c] + L[c]) : -1e30f;
    float emit = (lane < CC && len > 1) ? L[CC + c] : 0.f;

    for (int t = 1; t < len; ++t) {
        float m = alpha;
        #pragma unroll
        for (int o = 16; o; o >>= 1) m = fmaxf(m, __shfl_xor_sync(~0u, m, o));
        float p = __expf(alpha - m);
        float s = 0.f;
        #pragma unroll
        for (int i = 0; i < CC; ++i)
            s += __shfl_sync(~0u, p, i) * E[i];
        float na = m + __logf(s) + emit;
        if (t + 1 < len) emit = (lane < CC) ? L[(t + 1) * CC + c] : 0.f;
        alpha = (lane < CC) ? na : -1e30f;
    }

    float v = (lane < CC) ? (alpha + endsc[c]) : -1e30f;
    float m = v;
    #pragma unroll
    for (int o = 16; o; o >>= 1) m = fmaxf(m, __shfl_xor_sync(~0u, m, o));
    float s = __expf(v - m);
    if (lane >= CC) s = 0.f;
    #pragma unroll
    for (int o = 16; o; o >>= 1) s += __shfl_xor_sync(~0u, s, o);
    float logZ = m + __logf(s);

    float es = 0.f;
    for (int t = lane; t < len; t += 32) es += L[t * CC + tg[t]];
    float ts = 0.f;
    for (int t = lane; t < len - 1; t += 32) ts += trans[tg[t] * CC + tg[t + 1]];
    float g = es + ts;
    #pragma unroll
    for (int o = 16; o; o >>= 1) g += __shfl_xor_sync(~0u, g, o);
    if (lane == 0) {
        float gold = g + start[tg[0]] + endsc[tg[len - 1]];
        d_loss[b] = logZ - gold;
    }
}

// ---------------- K6: mean reduce ----------------
__global__ void __launch_bounds__(64) k6_mean(float* out) {
    __shared__ float sh[64];
    int tid = threadIdx.x;
    sh[tid] = d_loss[tid];
    __syncthreads();
    for (int o = 32; o; o >>= 1) {
        if (tid < o) sh[tid] += sh[tid + o];
        __syncthreads();
    }
    if (tid == 0) out[0] = sh[0] * (1.f / BB);
}

// ---------------- launch ----------------
extern "C" void kernel_launch(void* const* d_in, const int* in_sizes, int n_in,
                              void* d_out, int out_size) {
    const int*   words   = (const int*)d_in[0];
    const int*   seq_len = (const int*)d_in[1];
    const int*   target  = (const int*)d_in[2];
    const float* embed   = (const float*)d_in[3];
    const float* gamma   = (const float*)d_in[4];
    const float* beta    = (const float*)d_in[5];
    const float* wihf    = (const float*)d_in[6];
    const float* whhf    = (const float*)d_in[7];
    const float* bf      = (const float*)d_in[8];
    const float* wihb    = (const float*)d_in[9];
    const float* whhb    = (const float*)d_in[10];
    const float* bb      = (const float*)d_in[11];
    const float* fcw     = (const float*)d_in[12];
    const float* fcb     = (const float*)d_in[13];
    const float* trans   = (const float*)d_in[14];
    const float* startsc = (const float*)d_in[15];
    const float* endsc   = (const float*)d_in[16];
    float* out = (float*)d_out;

    size_t hsmem = (size_t)(104 * 72) * sizeof(uint);   // 29952 B
    cudaFuncSetAttribute(k3_lstm, cudaFuncAttributeMaxDynamicSharedMemorySize,
                         (int)hsmem);
    cudaFuncSetAttribute(k4_fc, cudaFuncAttributeMaxDynamicSharedMemorySize,
                         K4SMEM);

    k1_embed_ln<<<TT * BB / 8, 256>>>(words, embed, gamma, beta);
    {
        dim3 g(2 * G4 / 64, TT * BB / 128);   // 25 x 256
        k2_gemm<<<g, 256>>>(wihf, wihb, bf, bb);
    }
    k3_lstm<<<2 * NBD, 128, hsmem>>>(whhf, whhb, seq_len);
    k4_fc<<<TT, 128, K4SMEM>>>(fcw, fcb);
    k5_crf<<<BB, 32>>>(seq_len, target, trans, startsc, endsc);
    k6_mean<<<1, 64>>>(out);
}

// round 16
// speedup vs baseline: 1.1745x; 1.0060x over previous
#include <cuda_runtime.h>
#include <cuda_bf16.h>
#include <math.h>

#define TT 512
#define BB 64
#define EE 256
#define HH 200
#define G4 800
#define CC 20
#define NBD 50   // blocks per direction in LSTM kernel
#define HSL 4    // h-units per block (HH / NBD)
#define KT3 13   // k16-tiles covering HH=200 (pad to 208)

typedef unsigned int uint;

// ---------------- device scratch (no allocations allowed) ----------------
__device__ uint  d_xh[TT * BB * (EE / 2)];        // LN'd embeddings bf16x2
__device__ uint  d_Gh[2 * TT * G4 * 32];          // gates_x bf16x2 (batch pairs)
__device__ uint  d_hallh[2 * (TT + 1) * NBD * 128]; // h history bf16x2 [dir][slot][sl][u*32+bp]
__device__ float d_logits[BB * TT * CC];          // log_softmax outputs [b][t][c]
__device__ float d_loss[BB];
__device__ unsigned d_flagsp[2][NBD][32];         // flags spread 128B apart

#define HSLOT 6400           // uints per history slot (NBD*128)
#define HDIR  ((TT + 1) * HSLOT)

__device__ __forceinline__ uint pkbf(float lo, float hi) {
    uint r;
    asm("cvt.rn.bf16x2.f32 %0, %1, %2;" : "=r"(r) : "f"(hi), "f"(lo));
    return r;
}
__device__ __forceinline__ float bflo(uint v) { return __uint_as_float(v << 16); }
__device__ __forceinline__ float bfhi(uint v) { return __uint_as_float(v & 0xffff0000u); }
__device__ __forceinline__ float sigf(float x)  { return 1.f / (1.f + __expf(-x)); }
__device__ __forceinline__ float tanhfast(float x) { return 1.f - 2.f / (__expf(2.f * x) + 1.f); }

#define MMA_BF16(ACC, A, B0, B1)                                           \
    asm volatile(                                                          \
        "mma.sync.aligned.m16n8k16.row.col.f32.bf16.bf16.f32 "             \
        "{%0,%1,%2,%3}, {%4,%5,%6,%7}, {%8,%9}, {%0,%1,%2,%3};"            \
        : "+f"((ACC)[0]), "+f"((ACC)[1]), "+f"((ACC)[2]), "+f"((ACC)[3])   \
        : "r"((A)[0]), "r"((A)[1]), "r"((A)[2]), "r"((A)[3]),              \
          "r"(B0), "r"(B1))

// ---------------- K1: embedding + LayerNorm -> bf16x2; block 0 also inits ----------------
__global__ void __launch_bounds__(256) k1_embed_ln(
    const int* __restrict__ words, const float* __restrict__ embed,
    const float* __restrict__ gamma, const float* __restrict__ beta)
{
    if (blockIdx.x == 0) {
        int t0 = threadIdx.x;
        for (int i = t0; i < HSLOT; i += 256) {
            d_hallh[i] = 0u;                              // dir0, slot 0
            d_hallh[HDIR + (size_t)TT * HSLOT + i] = 0u;  // dir1, slot TT
        }
        for (int i = t0; i < 2 * NBD * 32; i += 256) ((unsigned*)d_flagsp)[i] = 0u;
    }

    int wid = threadIdx.x >> 5, lane = threadIdx.x & 31;
    int tok = blockIdx.x * 8 + wid;          // tok = t*64 + b
    int t = tok >> 6, b = tok & 63;
    int word = words[b * TT + t];
    const float4* src = (const float4*)(embed + (size_t)word * EE);
    float4 v0 = src[lane * 2], v1 = src[lane * 2 + 1];
    float s = v0.x + v0.y + v0.z + v0.w + v1.x + v1.y + v1.z + v1.w;
    float q = v0.x*v0.x + v0.y*v0.y + v0.z*v0.z + v0.w*v0.w
            + v1.x*v1.x + v1.y*v1.y + v1.z*v1.z + v1.w*v1.w;
    #pragma unroll
    for (int o = 16; o; o >>= 1) {
        s += __shfl_xor_sync(~0u, s, o);
        q += __shfl_xor_sync(~0u, q, o);
    }
    float mu  = s * (1.f / EE);
    float var = q * (1.f / EE) - mu * mu;
    float rs  = rsqrtf(var + 1e-5f);
    const float4* g4 = (const float4*)gamma;
    const float4* bt4 = (const float4*)beta;
    float4 ga = g4[lane*2], gb = g4[lane*2+1];
    float4 ba = bt4[lane*2], bb = bt4[lane*2+1];
    float o0x = (v0.x-mu)*rs*ga.x + ba.x,  o0y = (v0.y-mu)*rs*ga.y + ba.y;
    float o0z = (v0.z-mu)*rs*ga.z + ba.z,  o0w = (v0.w-mu)*rs*ga.w + ba.w;
    float o1x = (v1.x-mu)*rs*gb.x + bb.x,  o1y = (v1.y-mu)*rs*gb.y + bb.y;
    float o1z = (v1.z-mu)*rs*gb.z + bb.z,  o1w = (v1.w-mu)*rs*gb.w + bb.w;
    uint4 pk;
    pk.x = pkbf(o0x, o0y);  pk.y = pkbf(o0z, o0w);
    pk.z = pkbf(o1x, o1y);  pk.w = pkbf(o1z, o1w);
    *(uint4*)(d_xh + (size_t)tok * 128 + lane * 4) = pk;
}

// ---------------- K2: bf16 TC GEMM, double-buffered + staged coalesced epilogue ----------------
__global__ void __launch_bounds__(256) k2_gemm(
    const float* __restrict__ wihf, const float* __restrict__ wihb,
    const float* __restrict__ bf,   const float* __restrict__ bbias)
{
    __shared__ uint As2[2][128 * 12];   // [buf][m][k/2] bf16x2
    __shared__ uint Bs2[2][64 * 12];
    __shared__ uint stage[64 * 68];     // epilogue staging

    int tid = threadIdx.x;
    int m0 = blockIdx.y * 128, n0 = blockIdx.x * 64;
    int wid = tid >> 5, lane = tid & 31;
    int wm = wid & 3, wn = wid >> 2;            // warp grid 4 x 2
    int gid = lane >> 2, ctid = lane & 3;

    float acc[2][4][4];
    #pragma unroll
    for (int mi = 0; mi < 2; ++mi)
        #pragma unroll
        for (int ni = 0; ni < 4; ++ni)
            #pragma unroll
            for (int r = 0; r < 4; ++r) acc[mi][ni][r] = 0.f;

    int arow = tid >> 1, apart = tid & 1;
    int brow = tid >> 2, bq = tid & 3;
    int nglob = n0 + brow;
    const float* wrow = (nglob < G4) ? (wihf + (size_t)nglob * EE)
                                     : (wihb + (size_t)(nglob - G4) * EE);

    {
        uint4 aReg = *(const uint4*)(d_xh + (size_t)(m0 + arow) * 128 + apart * 4);
        float4 bReg = *(const float4*)(wrow + bq * 4);
        uint* dst = As2[0] + arow * 12 + apart * 4;
        dst[0] = aReg.x; dst[1] = aReg.y; dst[2] = aReg.z; dst[3] = aReg.w;
        uint* db = Bs2[0] + brow * 12 + bq * 2;
        db[0] = pkbf(bReg.x, bReg.y);
        db[1] = pkbf(bReg.z, bReg.w);
    }
    __syncthreads();

    for (int it = 0; it < 16; ++it) {
        int p = it & 1;

        uint afr[2][4], bfr[4][2];
        #pragma unroll
        for (int mi = 0; mi < 2; ++mi) {
            int mb = wm * 32 + mi * 16;
            const uint* ap = As2[p] + (mb + gid) * 12 + ctid;
            afr[mi][0] = ap[0];
            afr[mi][1] = ap[8 * 12];
            afr[mi][2] = ap[4];
            afr[mi][3] = ap[8 * 12 + 4];
        }
        #pragma unroll
        for (int ni = 0; ni < 4; ++ni) {
            int nb = wn * 32 + ni * 8;
            const uint* bp = Bs2[p] + (nb + gid) * 12 + ctid;
            bfr[ni][0] = bp[0];
            bfr[ni][1] = bp[4];
        }

        uint4 aReg;
        float4 bReg;
        if (it + 1 < 16) {
            int k0 = (it + 1) * 16;
            aReg = *(const uint4*)(d_xh + (size_t)(m0 + arow) * 128 + (k0 >> 1) + apart * 4);
            bReg = *(const float4*)(wrow + k0 + bq * 4);
        }

        #pragma unroll
        for (int mi = 0; mi < 2; ++mi)
            #pragma unroll
            for (int ni = 0; ni < 4; ++ni)
                MMA_BF16(acc[mi][ni], afr[mi], bfr[ni][0], bfr[ni][1]);

        if (it + 1 < 16) {
            uint* dst = As2[p ^ 1] + arow * 12 + apart * 4;
            dst[0] = aReg.x; dst[1] = aReg.y; dst[2] = aReg.z; dst[3] = aReg.w;
            uint* db = Bs2[p ^ 1] + brow * 12 + bq * 2;
            db[0] = pkbf(bReg.x, bReg.y);
            db[1] = pkbf(bReg.z, bReg.w);
        }
        __syncthreads();
    }

    #pragma unroll
    for (int mi = 0; mi < 2; ++mi)
        #pragma unroll
        for (int ni = 0; ni < 4; ++ni)
            #pragma unroll
            for (int r = 0; r < 4; ++r) {
                int n_local = wn * 32 + ni * 8 + 2 * ctid + (r & 1);
                int n = n0 + n_local;
                int dir = (n >= G4) ? 1 : 0;
                int rr = n - dir * G4;
                float val = acc[mi][ni][r] + (dir ? bbias[rr] : bf[rr]);
                float pv = __shfl_xor_sync(~0u, val, 4);   // partner batch b+1
                if ((gid & 1) == 0) {
                    int off = wm * 32 + mi * 16 + gid + (r >> 1) * 8;   // 0..127
                    int tl = off >> 6, bp = (off & 63) >> 1;
                    stage[n_local * 68 + tl * 32 + bp] = pkbf(val, pv);
                }
            }
    __syncthreads();

    {
        int t0 = m0 >> 6;
        int row = tid >> 2, ch = tid & 3;
        int n = n0 + row;
        int dir = (n >= G4) ? 1 : 0;
        int rr = n - dir * G4;
        #pragma unroll
        for (int j = 0; j < 4; ++j) {
            int off = ch * 16 + j * 4;
            int tl = off >> 5, bp = off & 31;
            uint4 v = *(const uint4*)&stage[row * 68 + off];
            *(uint4*)&d_Gh[((size_t)dir * TT * G4 + (size_t)(t0 + tl) * G4 + rr) * 32 + bp] = v;
        }
    }
}

// ---------------- K3: persistent BiLSTM, bf16 tensor-core recurrence (R9) ----------------
__global__ void __launch_bounds__(128, 1) k3_lstm(
    const float* __restrict__ whhf, const float* __restrict__ whhb,
    const int* __restrict__ seq_len)
{
    extern __shared__ uint hsh2[];            // [104][72] bf16x2 (k-pair, n) 29952 B

    int tid = threadIdx.x;
    int dir = blockIdx.x / NBD;
    int sl  = blockIdx.x % NBD;
    int j0  = sl * HSL;
    const float* whh = dir ? whhb : whhf;

    int wid = tid >> 5, lane = tid & 31;
    int gid = lane >> 2, ctid = lane & 3;
    int u   = gid & 3;
    int q1  = gid >> 2;
    int bnw = wid * 16;
    int b0  = bnw + q1 * 8 + 2 * ctid;

    uint aw[KT3][4];
    {
        int rowA = q1 * HH + j0 + u;
        int rowB = (q1 + 2) * HH + j0 + u;
        #pragma unroll
        for (int kt = 0; kt < KT3; ++kt) {
            int kA = kt * 16 + 2 * ctid;
            int kC = kA + 8;
            float a0 = whh[(size_t)rowA * HH + kA];
            float a1 = whh[(size_t)rowA * HH + kA + 1];
            float b0v = whh[(size_t)rowB * HH + kA];
            float b1v = whh[(size_t)rowB * HH + kA + 1];
            float a2 = (kC < HH) ? whh[(size_t)rowA * HH + kC] : 0.f;
            float a3 = (kC + 1 < HH) ? whh[(size_t)rowA * HH + kC + 1] : 0.f;
            float b2v = (kC < HH) ? whh[(size_t)rowB * HH + kC] : 0.f;
            float b3v = (kC + 1 < HH) ? whh[(size_t)rowB * HH + kC + 1] : 0.f;
            aw[kt][0] = pkbf(a0, a1);
            aw[kt][1] = pkbf(b0v, b1v);
            aw[kt][2] = pkbf(a2, a3);
            aw[kt][3] = pkbf(b2v, b3v);
        }
    }

    for (int i = tid; i < 4 * 72; i += 128) hsh2[100 * 72 + i] = 0u;

    int len0 = seq_len[b0], len1 = seq_len[b0 + 1];
    float c0 = 0.f, c1 = 0.f, hp0 = 0.f, hp1 = 0.f;
    uint pk = 0u;

    uint* hbase = d_hallh + (size_t)dir * HDIR;
    unsigned* flg = &d_flagsp[dir][0][0];

    int ls2 = tid >> 1, lhalf = tid & 1;
    int lslice = ls2 + (ls2 >= sl ? 1 : 0);
    bool loader = (tid < 2 * (NBD - 1));

    int goff[4];
    #pragma unroll
    for (int q = 0; q < 4; ++q)
        goff[q] = (q * HH + j0 + u) * 32 + (b0 >> 1);

    const uint* Gd = d_Gh + (size_t)dir * TT * G4 * 32;

    uint xg[4];
    {
        int t0 = dir ? (TT - 1) : 0;
        const uint* Gt = Gd + (size_t)t0 * G4 * 32;
        #pragma unroll
        for (int q = 0; q < 4; ++q) xg[q] = __ldcg(Gt + goff[q]);
    }

    for (int st = 0; st < TT; ++st) {
        int t = dir ? (TT - 1 - st) : st;
        int rs = dir ? (t + 1) : t;
        int ws = dir ? t : (t + 1);

        {
            uint ppk = __shfl_xor_sync(~0u, pk, 4);
            if ((u & 1) == 0) {
                uint olo = __byte_perm(pk, ppk, 0x5410);
                uint ohi = __byte_perm(pk, ppk, 0x7632);
                *(uint2*)&hsh2[(2 * sl + (u >> 1)) * 72 + b0] = make_uint2(olo, ohi);
            }
        }

        if (loader) {
            unsigned v;
            const unsigned* fp = flg + lslice * 32;
            do {
                asm volatile("ld.acquire.gpu.u32 %0, [%1];" : "=r"(v) : "l"(fp));
            } while (v < (unsigned)st);
            const uint4* src = (const uint4*)(hbase + (size_t)rs * HSLOT + lslice * 128);
            int r0 = 2 * lslice;
            #pragma unroll
            for (int g = 0; g < 4; ++g) {
                int co = lhalf * 4 + g;
                int base = co * 8;
                uint4 A0 = __ldcg(src + 0 * 8 + co);
                uint4 A1 = __ldcg(src + 1 * 8 + co);
                uint4 A2 = __ldcg(src + 2 * 8 + co);
                uint4 A3 = __ldcg(src + 3 * 8 + co);
                uint4 o;
                o.x = __byte_perm(A0.x, A1.x, 0x5410);
                o.y = __byte_perm(A0.x, A1.x, 0x7632);
                o.z = __byte_perm(A0.y, A1.y, 0x5410);
                o.w = __byte_perm(A0.y, A1.y, 0x7632);
                *(uint4*)&hsh2[r0 * 72 + base] = o;
                o.x = __byte_perm(A0.z, A1.z, 0x5410);
                o.y = __byte_perm(A0.z, A1.z, 0x7632);
                o.z = __byte_perm(A0.w, A1.w, 0x5410);
                o.w = __byte_perm(A0.w, A1.w, 0x7632);
                *(uint4*)&hsh2[r0 * 72 + base + 4] = o;
                o.x = __byte_perm(A2.x, A3.x, 0x5410);
                o.y = __byte_perm(A2.x, A3.x, 0x7632);
                o.z = __byte_perm(A2.y, A3.y, 0x5410);
                o.w = __byte_perm(A2.y, A3.y, 0x7632);
                *(uint4*)&hsh2[(r0 + 1) * 72 + base] = o;
                o.x = __byte_perm(A2.z, A3.z, 0x5410);
                o.y = __byte_perm(A2.z, A3.z, 0x7632);
                o.z = __byte_perm(A2.w, A3.w, 0x5410);
                o.w = __byte_perm(A2.w, A3.w, 0x7632);
                *(uint4*)&hsh2[(r0 + 1) * 72 + base + 4] = o;
            }
        }
        __syncthreads();

        float acc0[4] = {0.f, 0.f, 0.f, 0.f};
        float acc1[4] = {0.f, 0.f, 0.f, 0.f};
        #pragma unroll
        for (int kt = 0; kt < KT3; ++kt) {
            const uint* hk = hsh2 + (kt * 8 + ctid) * 72;
            uint b00 = hk[bnw + gid];
            uint b01 = hk[4 * 72 + bnw + gid];
            uint b10 = hk[bnw + 8 + gid];
            uint b11 = hk[4 * 72 + bnw + 8 + gid];
            MMA_BF16(acc0, aw[kt], b00, b01);
            MMA_BF16(acc1, aw[kt], b10, b11);
        }

        float s0 = q1 ? acc0[0] : acc1[0];
        float s1 = q1 ? acc0[1] : acc1[1];
        float s2 = q1 ? acc0[2] : acc1[2];
        float s3 = q1 ? acc0[3] : acc1[3];
        float o0 = __shfl_xor_sync(~0u, s0, 16);
        float o1 = __shfl_xor_sync(~0u, s1, 16);
        float o2 = __shfl_xor_sync(~0u, s2, 16);
        float o3 = __shfl_xor_sync(~0u, s3, 16);
        float m0 = q1 ? acc1[0] : acc0[0];
        float m1 = q1 ? acc1[1] : acc0[1];
        float m2 = q1 ? acc1[2] : acc0[2];
        float m3 = q1 ? acc1[3] : acc0[3];
        float gi0 = q1 ? o0 : m0,  gf0 = q1 ? m0 : o0;
        float gg0 = q1 ? o2 : m2,  go0 = q1 ? m2 : o2;
        float gi1 = q1 ? o1 : m1,  gf1 = q1 ? m1 : o1;
        float gg1 = q1 ? o3 : m3,  go1 = q1 ? m3 : o3;

        {
            float cn = sigf(gf0 + bflo(xg[1])) * c0
                     + sigf(gi0 + bflo(xg[0])) * tanhfast(gg0 + bflo(xg[2]));
            float hn = sigf(go0 + bflo(xg[3])) * tanhfast(cn);
            bool valid = (t < len0);
            hp0 = valid ? hn : hp0;
            c0  = valid ? cn : c0;
        }
        {
            float cn = sigf(gf1 + bfhi(xg[1])) * c1
                     + sigf(gi1 + bfhi(xg[0])) * tanhfast(gg1 + bfhi(xg[2]));
            float hn = sigf(go1 + bfhi(xg[3])) * tanhfast(cn);
            bool valid = (t < len1);
            hp1 = valid ? hn : hp1;
            c1  = valid ? cn : c1;
        }

        pk = pkbf(hp0, hp1);
        __stcg(hbase + (size_t)ws * HSLOT + sl * 128 + u * 32 + (b0 >> 1), pk);

        __syncthreads();
        if (tid == 0) {
            asm volatile("fence.acq_rel.gpu;" ::: "memory");
            asm volatile("st.relaxed.gpu.u32 [%0], %1;"
                         :: "l"(flg + sl * 32), "r"((unsigned)(st + 1)) : "memory");
        }

        if (st + 1 < TT) {
            int tn = dir ? (TT - 2 - st) : (st + 1);
            const uint* Gt = Gd + (size_t)tn * G4 * 32;
            #pragma unroll
            for (int q = 0; q < 4; ++q) xg[q] = __ldcg(Gt + goff[q]);
        }
    }
}

// ---------------- K4: FC + log_softmax via bf16 tensor cores (block = one t) ----------------
#define K4SMEM ((64 * 201 + 24 * 201) * 4)
__global__ void __launch_bounds__(128) k4_fc(
    const float* __restrict__ fcw, const float* __restrict__ fcb)
{
    extern __shared__ uint k4u[];
    uint* Ah = k4u;                 // [64][201]
    uint* Bsw = k4u + 64 * 201;     // [24][201]
    __shared__ float fbsh[24];

    int tid = threadIdx.x;
    int t = blockIdx.x;
    int wid = tid >> 5, lane = tid & 31;
    int gid = lane >> 2, ctid = lane & 3;

    for (int i = tid; i < 24 * 200; i += 128) {
        int c = i / 200, j = i % 200;
        uint v = 0u;
        if (c < CC) {
            float w0 = fcw[c * 400 + 2 * j];
            float w1 = fcw[c * 400 + 2 * j + 1];
            v = pkbf(w0, w1);
        }
        Bsw[c * 201 + j] = v;
    }
    if (tid < 24) fbsh[tid] = (tid < CC) ? fcb[tid] : 0.f;

    for (int idx = tid; idx < 6400; idx += 128) {
        int j = idx >> 5, bp = idx & 31;
        int dirr = (j >= 100) ? 1 : 0;
        int jj = 2 * j - dirr * 2 * HH + 0;
        size_t base = (size_t)dirr * HDIR
                    + (size_t)(dirr ? t : (t + 1)) * HSLOT;
        uint U0 = d_hallh[base + (jj >> 2) * 128 + (jj & 3) * 32 + bp];
        int jk = jj + 1;
        uint U1 = d_hallh[base + (jk >> 2) * 128 + (jk & 3) * 32 + bp];
        Ah[(2 * bp) * 201 + j]     = __byte_perm(U0, U1, 0x5410);
        Ah[(2 * bp + 1) * 201 + j] = __byte_perm(U0, U1, 0x7632);
    }
    __syncthreads();

    float acc[3][4] = {{0,0,0,0},{0,0,0,0},{0,0,0,0}};
    int mb = wid * 16;
    #pragma unroll 5
    for (int kt = 0; kt < 25; ++kt) {
        uint afr[4];
        const uint* ap = Ah + (mb + gid) * 201 + kt * 8 + ctid;
        afr[0] = ap[0];
        afr[1] = ap[8 * 201];
        afr[2] = ap[4];
        afr[3] = ap[8 * 201 + 4];
        #pragma unroll
        for (int ni = 0; ni < 3; ++ni) {
            const uint* bp_ = Bsw + (ni * 8 + gid) * 201 + kt * 8 + ctid;
            MMA_BF16(acc[ni], afr, bp_[0], bp_[4]);
        }
    }

    #pragma unroll
    for (int rs = 0; rs < 2; ++rs) {
        int b = mb + gid + rs * 8;
        float v[6];
        float mx = -1e30f;
        #pragma unroll
        for (int ni = 0; ni < 3; ++ni) {
            #pragma unroll
            for (int k = 0; k < 2; ++k) {
                int cls = ni * 8 + 2 * ctid + k;
                float x = acc[ni][rs * 2 + k] + fbsh[cls];
                if (cls >= CC) x = -1e30f;
                v[ni * 2 + k] = x;
                mx = fmaxf(mx, x);
            }
        }
        mx = fmaxf(mx, __shfl_xor_sync(~0u, mx, 1));
        mx = fmaxf(mx, __shfl_xor_sync(~0u, mx, 2));
        float s = 0.f;
        #pragma unroll
        for (int k = 0; k < 6; ++k) s += __expf(v[k] - mx);
        s += __shfl_xor_sync(~0u, s, 1);
        s += __shfl_xor_sync(~0u, s, 2);
        float lse = mx + __logf(s);
        #pragma unroll
        for (int ni = 0; ni < 3; ++ni)
            #pragma unroll
            for (int k = 0; k < 2; ++k) {
                int cls = ni * 8 + 2 * ctid + k;
                if (cls < CC)
                    d_logits[((size_t)b * TT + t) * CC + cls] = v[ni * 2 + k] - lse;
            }
    }
}

// ---------------- K5: CRF NLL, exp-factored + lane0-offset logsumexp ----------------
__global__ void __launch_bounds__(32) k5_crf(
    const int* __restrict__ seq_len, const int* __restrict__ target,
    const float* __restrict__ trans, const float* __restrict__ start,
    const float* __restrict__ endsc)
{
    int b = blockIdx.x;
    int lane = threadIdx.x;
    int c = (lane < CC) ? lane : 0;
    int len = seq_len[b];
    const float* L = d_logits + (size_t)b * TT * CC;
    const int* tg = target + (size_t)b * TT;

    float E[CC];
    #pragma unroll
    for (int i = 0; i < CC; ++i)
        E[i] = (lane < CC) ? __expf(trans[i * CC + c]) : 0.f;

    float alpha = (lane < CC) ? (start[c] + L[c]) : -1e30f;
    float emit = (lane < CC && len > 1) ? L[CC + c] : 0.f;

    for (int t = 1; t < len; ++t) {
        // offset m: any value within ~80 of max is exact for logsumexp.
        // lane0's alpha is representative (small inter-class spread);
        // recompute the true max every 16 steps as a safety net.
        float m;
        if ((t & 15) == 1) {
            m = alpha;
            #pragma unroll
            for (int o = 16; o; o >>= 1) m = fmaxf(m, __shfl_xor_sync(~0u, m, o));
        } else {
            m = __shfl_sync(~0u, alpha, 0);
        }
        float p = __expf(alpha - m);
        // 4-way split accumulation: shortens the FADD chain 20*4 -> ~5*4+2 levels
        float sa = 0.f, sb = 0.f, sc = 0.f, sd = 0.f;
        #pragma unroll
        for (int i = 0; i < 5; ++i) {
            sa += __shfl_sync(~0u, p, i)      * E[i];
            sb += __shfl_sync(~0u, p, i + 5)  * E[i + 5];
            sc += __shfl_sync(~0u, p, i + 10) * E[i + 10];
            sd += __shfl_sync(~0u, p, i + 15) * E[i + 15];
        }
        float s = (sa + sb) + (sc + sd);
        float na = m + __logf(s) + emit;
        if (t + 1 < len) emit = (lane < CC) ? L[(t + 1) * CC + c] : 0.f;
        alpha = (lane < CC) ? na : -1e30f;
    }

    float v = (lane < CC) ? (alpha + endsc[c]) : -1e30f;
    float m = v;
    #pragma unroll
    for (int o = 16; o; o >>= 1) m = fmaxf(m, __shfl_xor_sync(~0u, m, o));
    float s = __expf(v - m);
    if (lane >= CC) s = 0.f;
    #pragma unroll
    for (int o = 16; o; o >>= 1) s += __shfl_xor_sync(~0u, s, o);
    float logZ = m + __logf(s);

    float es = 0.f;
    for (int t = lane; t < len; t += 32) es += L[t * CC + tg[t]];
    float ts = 0.f;
    for (int t = lane; t < len - 1; t += 32) ts += trans[tg[t] * CC + tg[t + 1]];
    float g = es + ts;
    #pragma unroll
    for (int o = 16; o; o >>= 1) g += __shfl_xor_sync(~0u, g, o);
    if (lane == 0) {
        float gold = g + start[tg[0]] + endsc[tg[len - 1]];
        d_loss[b] = logZ - gold;
    }
}

// ---------------- K6: mean reduce ----------------
__global__ void __launch_bounds__(64) k6_mean(float* out) {
    __shared__ float sh[64];
    int tid = threadIdx.x;
    sh[tid] = d_loss[tid];
    __syncthreads();
    for (int o = 32; o; o >>= 1) {
        if (tid < o) sh[tid] += sh[tid + o];
        __syncthreads();
    }
    if (tid == 0) out[0] = sh[0] * (1.f / BB);
}

// ---------------- launch ----------------
extern "C" void kernel_launch(void* const* d_in, const int* in_sizes, int n_in,
                              void* d_out, int out_size) {
    const int*   words   = (const int*)d_in[0];
    const int*   seq_len = (const int*)d_in[1];
    const int*   target  = (const int*)d_in[2];
    const float* embed   = (const float*)d_in[3];
    const float* gamma   = (const float*)d_in[4];
    const float* beta    = (const float*)d_in[5];
    const float* wihf    = (const float*)d_in[6];
    const float* whhf    = (const float*)d_in[7];
    const float* bf      = (const float*)d_in[8];
    const float* wihb    = (const float*)d_in[9];
    const float* whhb    = (const float*)d_in[10];
    const float* bb      = (const float*)d_in[11];
    const float* fcw     = (const float*)d_in[12];
    const float* fcb     = (const float*)d_in[13];
    const float* trans   = (const float*)d_in[14];
    const float* startsc = (const float*)d_in[15];
    const float* endsc   = (const float*)d_in[16];
    float* out = (float*)d_out;

    size_t hsmem = (size_t)(104 * 72) * sizeof(uint);   // 29952 B
    cudaFuncSetAttribute(k3_lstm, cudaFuncAttributeMaxDynamicSharedMemorySize,
                         (int)hsmem);
    cudaFuncSetAttribute(k4_fc, cudaFuncAttributeMaxDynamicSharedMemorySize,
                         K4SMEM);

    k1_embed_ln<<<TT * BB / 8, 256>>>(words, embed, gamma, beta);
    {
        dim3 g(2 * G4 / 64, TT * BB / 128);   // 25 x 256
        k2_gemm<<<g, 256>>>(wihf, wihb, bf, bb);
    }
    k3_lstm<<<2 * NBD, 128, hsmem>>>(whhf, whhb, seq_len);
    k4_fc<<<TT, 128, K4SMEM>>>(fcw, fcb);
    k5_crf<<<BB, 32>>>(seq_len, target, trans, startsc, endsc);
    k6_mean<<<1, 64>>>(out);
}

// round 17
// speedup vs baseline: 1.2808x; 1.0905x over previous
#include <cuda_runtime.h>
#include <cuda_bf16.h>
#include <math.h>

#define TT 512
#define BB 64
#define EE 256
#define HH 200
#define G4 800
#define CC 20
#define NBD 25   // blocks per direction in LSTM kernel
#define HSL 8    // h-units per block (HH / NBD)
#define KT3 13   // k16-tiles covering HH=200 (pad to 208)

typedef unsigned int uint;

// ---------------- device scratch (no allocations allowed) ----------------
__device__ uint  d_xh[TT * BB * (EE / 2)];        // LN'd embeddings bf16x2
__device__ uint  d_Gh[2 * TT * G4 * 32];          // gates_x bf16x2 (batch pairs)
__device__ uint  d_hallh[2 * (TT + 1) * 6400];    // h history bf16x2, linear jj*32+bp per slot
__device__ float d_logits[BB * TT * CC];          // log_softmax outputs [b][t][c]
__device__ float d_loss[BB];
__device__ unsigned d_flagsp[2][64][32];          // flags spread 128B apart

#define HSLOT 6400           // uints per history slot
#define HDIR  ((TT + 1) * HSLOT)

__device__ __forceinline__ uint pkbf(float lo, float hi) {
    uint r;
    asm("cvt.rn.bf16x2.f32 %0, %1, %2;" : "=r"(r) : "f"(hi), "f"(lo));
    return r;
}
__device__ __forceinline__ float bflo(uint v) { return __uint_as_float(v << 16); }
__device__ __forceinline__ float bfhi(uint v) { return __uint_as_float(v & 0xffff0000u); }
__device__ __forceinline__ float sigf(float x)  { return 1.f / (1.f + __expf(-x)); }
__device__ __forceinline__ float tanhfast(float x) { return 1.f - 2.f / (__expf(2.f * x) + 1.f); }

#define MMA_BF16(ACC, A, B0, B1)                                           \
    asm volatile(                                                          \
        "mma.sync.aligned.m16n8k16.row.col.f32.bf16.bf16.f32 "             \
        "{%0,%1,%2,%3}, {%4,%5,%6,%7}, {%8,%9}, {%0,%1,%2,%3};"            \
        : "+f"((ACC)[0]), "+f"((ACC)[1]), "+f"((ACC)[2]), "+f"((ACC)[3])   \
        : "r"((A)[0]), "r"((A)[1]), "r"((A)[2]), "r"((A)[3]),              \
          "r"(B0), "r"(B1))

// ---------------- K1: embedding + LayerNorm -> bf16x2; block 0 also inits ----------------
__global__ void __launch_bounds__(256) k1_embed_ln(
    const int* __restrict__ words, const float* __restrict__ embed,
    const float* __restrict__ gamma, const float* __restrict__ beta)
{
    if (blockIdx.x == 0) {
        int t0 = threadIdx.x;
        for (int i = t0; i < HSLOT; i += 256) {
            d_hallh[i] = 0u;                              // dir0, slot 0
            d_hallh[HDIR + (size_t)TT * HSLOT + i] = 0u;  // dir1, slot TT
        }
        for (int i = t0; i < 2 * 64 * 32; i += 256) ((unsigned*)d_flagsp)[i] = 0u;
    }

    int wid = threadIdx.x >> 5, lane = threadIdx.x & 31;
    int tok = blockIdx.x * 8 + wid;          // tok = t*64 + b
    int t = tok >> 6, b = tok & 63;
    int word = words[b * TT + t];
    const float4* src = (const float4*)(embed + (size_t)word * EE);
    float4 v0 = src[lane * 2], v1 = src[lane * 2 + 1];
    float s = v0.x + v0.y + v0.z + v0.w + v1.x + v1.y + v1.z + v1.w;
    float q = v0.x*v0.x + v0.y*v0.y + v0.z*v0.z + v0.w*v0.w
            + v1.x*v1.x + v1.y*v1.y + v1.z*v1.z + v1.w*v1.w;
    #pragma unroll
    for (int o = 16; o; o >>= 1) {
        s += __shfl_xor_sync(~0u, s, o);
        q += __shfl_xor_sync(~0u, q, o);
    }
    float mu  = s * (1.f / EE);
    float var = q * (1.f / EE) - mu * mu;
    float rs  = rsqrtf(var + 1e-5f);
    const float4* g4 = (const float4*)gamma;
    const float4* bt4 = (const float4*)beta;
    float4 ga = g4[lane*2], gb = g4[lane*2+1];
    float4 ba = bt4[lane*2], bb = bt4[lane*2+1];
    float o0x = (v0.x-mu)*rs*ga.x + ba.x,  o0y = (v0.y-mu)*rs*ga.y + ba.y;
    float o0z = (v0.z-mu)*rs*ga.z + ba.z,  o0w = (v0.w-mu)*rs*ga.w + ba.w;
    float o1x = (v1.x-mu)*rs*gb.x + bb.x,  o1y = (v1.y-mu)*rs*gb.y + bb.y;
    float o1z = (v1.z-mu)*rs*gb.z + bb.z,  o1w = (v1.w-mu)*rs*gb.w + bb.w;
    uint4 pk;
    pk.x = pkbf(o0x, o0y);  pk.y = pkbf(o0z, o0w);
    pk.z = pkbf(o1x, o1y);  pk.w = pkbf(o1z, o1w);
    *(uint4*)(d_xh + (size_t)tok * 128 + lane * 4) = pk;
}

// ---------------- K2: bf16 TC GEMM, double-buffered + staged coalesced epilogue ----------------
__global__ void __launch_bounds__(256) k2_gemm(
    const float* __restrict__ wihf, const float* __restrict__ wihb,
    const float* __restrict__ bf,   const float* __restrict__ bbias)
{
    __shared__ uint As2[2][128 * 12];   // [buf][m][k/2] bf16x2
    __shared__ uint Bs2[2][64 * 12];
    __shared__ uint stage[64 * 68];     // epilogue staging

    int tid = threadIdx.x;
    int m0 = blockIdx.y * 128, n0 = blockIdx.x * 64;
    int wid = tid >> 5, lane = tid & 31;
    int wm = wid & 3, wn = wid >> 2;            // warp grid 4 x 2
    int gid = lane >> 2, ctid = lane & 3;

    float acc[2][4][4];
    #pragma unroll
    for (int mi = 0; mi < 2; ++mi)
        #pragma unroll
        for (int ni = 0; ni < 4; ++ni)
            #pragma unroll
            for (int r = 0; r < 4; ++r) acc[mi][ni][r] = 0.f;

    int arow = tid >> 1, apart = tid & 1;
    int brow = tid >> 2, bq = tid & 3;
    int nglob = n0 + brow;
    const float* wrow = (nglob < G4) ? (wihf + (size_t)nglob * EE)
                                     : (wihb + (size_t)(nglob - G4) * EE);

    {
        uint4 aReg = *(const uint4*)(d_xh + (size_t)(m0 + arow) * 128 + apart * 4);
        float4 bReg = *(const float4*)(wrow + bq * 4);
        uint* dst = As2[0] + arow * 12 + apart * 4;
        dst[0] = aReg.x; dst[1] = aReg.y; dst[2] = aReg.z; dst[3] = aReg.w;
        uint* db = Bs2[0] + brow * 12 + bq * 2;
        db[0] = pkbf(bReg.x, bReg.y);
        db[1] = pkbf(bReg.z, bReg.w);
    }
    __syncthreads();

    for (int it = 0; it < 16; ++it) {
        int p = it & 1;

        uint afr[2][4], bfr[4][2];
        #pragma unroll
        for (int mi = 0; mi < 2; ++mi) {
            int mb = wm * 32 + mi * 16;
            const uint* ap = As2[p] + (mb + gid) * 12 + ctid;
            afr[mi][0] = ap[0];
            afr[mi][1] = ap[8 * 12];
            afr[mi][2] = ap[4];
            afr[mi][3] = ap[8 * 12 + 4];
        }
        #pragma unroll
        for (int ni = 0; ni < 4; ++ni) {
            int nb = wn * 32 + ni * 8;
            const uint* bp = Bs2[p] + (nb + gid) * 12 + ctid;
            bfr[ni][0] = bp[0];
            bfr[ni][1] = bp[4];
        }

        uint4 aReg;
        float4 bReg;
        if (it + 1 < 16) {
            int k0 = (it + 1) * 16;
            aReg = *(const uint4*)(d_xh + (size_t)(m0 + arow) * 128 + (k0 >> 1) + apart * 4);
            bReg = *(const float4*)(wrow + k0 + bq * 4);
        }

        #pragma unroll
        for (int mi = 0; mi < 2; ++mi)
            #pragma unroll
            for (int ni = 0; ni < 4; ++ni)
                MMA_BF16(acc[mi][ni], afr[mi], bfr[ni][0], bfr[ni][1]);

        if (it + 1 < 16) {
            uint* dst = As2[p ^ 1] + arow * 12 + apart * 4;
            dst[0] = aReg.x; dst[1] = aReg.y; dst[2] = aReg.z; dst[3] = aReg.w;
            uint* db = Bs2[p ^ 1] + brow * 12 + bq * 2;
            db[0] = pkbf(bReg.x, bReg.y);
            db[1] = pkbf(bReg.z, bReg.w);
        }
        __syncthreads();
    }

    #pragma unroll
    for (int mi = 0; mi < 2; ++mi)
        #pragma unroll
        for (int ni = 0; ni < 4; ++ni)
            #pragma unroll
            for (int r = 0; r < 4; ++r) {
                int n_local = wn * 32 + ni * 8 + 2 * ctid + (r & 1);
                int n = n0 + n_local;
                int dir = (n >= G4) ? 1 : 0;
                int rr = n - dir * G4;
                float val = acc[mi][ni][r] + (dir ? bbias[rr] : bf[rr]);
                float pv = __shfl_xor_sync(~0u, val, 4);   // partner batch b+1
                if ((gid & 1) == 0) {
                    int off = wm * 32 + mi * 16 + gid + (r >> 1) * 8;   // 0..127
                    int tl = off >> 6, bp = (off & 63) >> 1;
                    stage[n_local * 68 + tl * 32 + bp] = pkbf(val, pv);
                }
            }
    __syncthreads();

    {
        int t0 = m0 >> 6;
        int row = tid >> 2, ch = tid & 3;
        int n = n0 + row;
        int dir = (n >= G4) ? 1 : 0;
        int rr = n - dir * G4;
        #pragma unroll
        for (int j = 0; j < 4; ++j) {
            int off = ch * 16 + j * 4;
            int tl = off >> 5, bp = off & 31;
            uint4 v = *(const uint4*)&stage[row * 68 + off];
            *(uint4*)&d_Gh[((size_t)dir * TT * G4 + (size_t)(t0 + tl) * G4 + rr) * 32 + bp] = v;
        }
    }
}

// ---------------- K3: persistent BiLSTM, NBD=25, 256 threads, 8 units/block ----------------
__global__ void __launch_bounds__(256, 1) k3_lstm(
    const float* __restrict__ whhf, const float* __restrict__ whhb,
    const int* __restrict__ seq_len)
{
    extern __shared__ uint hsh2[];            // [104][72] bf16x2 (k-pair, n) 29952 B

    int tid = threadIdx.x;
    int dir = blockIdx.x / NBD;
    int sl  = blockIdx.x % NBD;
    int j0  = sl * HSL;
    const float* whh = dir ? whhb : whhf;

    int wid = tid >> 5, lane = tid & 31;
    int gid = lane >> 2, ctid = lane & 3;
    int u   = gid & 3;
    int q1  = gid >> 2;
    int mt  = wid & 1;            // m-tile within block (unit group of 4)
    int bg  = wid >> 1;           // batch group 0..3
    int bnw = bg * 16;
    int b0  = bnw + q1 * 8 + 2 * ctid;
    int ugl = j0 + mt * 4 + u;    // global unit

    // persistent bf16 A fragments (identical structure to R9, rows of unit ugl)
    uint aw[KT3][4];
    {
        int rowA = q1 * HH + ugl;
        int rowB = (q1 + 2) * HH + ugl;
        #pragma unroll
        for (int kt = 0; kt < KT3; ++kt) {
            int kA = kt * 16 + 2 * ctid;
            int kC = kA + 8;
            float a0 = whh[(size_t)rowA * HH + kA];
            float a1 = whh[(size_t)rowA * HH + kA + 1];
            float b0v = whh[(size_t)rowB * HH + kA];
            float b1v = whh[(size_t)rowB * HH + kA + 1];
            float a2 = (kC < HH) ? whh[(size_t)rowA * HH + kC] : 0.f;
            float a3 = (kC + 1 < HH) ? whh[(size_t)rowA * HH + kC + 1] : 0.f;
            float b2v = (kC < HH) ? whh[(size_t)rowB * HH + kC] : 0.f;
            float b3v = (kC + 1 < HH) ? whh[(size_t)rowB * HH + kC + 1] : 0.f;
            aw[kt][0] = pkbf(a0, a1);
            aw[kt][1] = pkbf(b0v, b1v);
            aw[kt][2] = pkbf(a2, a3);
            aw[kt][3] = pkbf(b2v, b3v);
        }
    }

    // zero pad rows 100..103 once
    for (int i = tid; i < 4 * 72; i += 256) hsh2[100 * 72 + i] = 0u;

    int len0 = seq_len[b0], len1 = seq_len[b0 + 1];
    float c0 = 0.f, c1 = 0.f, hp0 = 0.f, hp1 = 0.f;
    uint pk = 0u;

    uint* hbase = d_hallh + (size_t)dir * HDIR;
    unsigned* flg = &d_flagsp[dir][0][0];

    // loaders: 8 threads per foreign slice (24 slices, 192 threads)
    int s8 = tid >> 3, sub = tid & 7;
    int lslice = s8 + (s8 >= sl ? 1 : 0);
    int lup = sub >> 1, lhalf = sub & 1;
    bool loader = (tid < 8 * (NBD - 1));

    int goff[4];
    #pragma unroll
    for (int q = 0; q < 4; ++q)
        goff[q] = (q * HH + ugl) * 32 + (b0 >> 1);

    const uint* Gd = d_Gh + (size_t)dir * TT * G4 * 32;

    uint xg[4];
    {
        int t0 = dir ? (TT - 1) : 0;
        const uint* Gt = Gd + (size_t)t0 * G4 * 32;
        #pragma unroll
        for (int q = 0; q < 4; ++q) xg[q] = __ldcg(Gt + goff[q]);
    }
    __syncthreads();

    for (int st = 0; st < TT; ++st) {
        int t = dir ? (TT - 1 - st) : st;
        int rs = dir ? (t + 1) : t;
        int ws = dir ? t : (t + 1);

        // own slice: k-pair pack with partner unit (lane^4), even-u stores
        {
            uint ppk = __shfl_xor_sync(~0u, pk, 4);
            if ((u & 1) == 0) {
                uint olo = __byte_perm(pk, ppk, 0x5410);
                uint ohi = __byte_perm(pk, ppk, 0x7632);
                int row = sl * 4 + mt * 2 + (u >> 1);
                *(uint2*)&hsh2[row * 72 + b0] = make_uint2(olo, ohi);
            }
        }

        // foreign slices: poll producer flag, load, PRMT k-repack
        if (loader) {
            unsigned v;
            const unsigned* fp = flg + lslice * 32;
            do {
                asm volatile("ld.acquire.gpu.u32 %0, [%1];" : "=r"(v) : "l"(fp));
            } while (v < (unsigned)st);
            const uint* sb = hbase + (size_t)rs * HSLOT + lslice * 256;
            const uint4* srcA = (const uint4*)(sb + (2 * lup) * 32 + lhalf * 16);
            const uint4* srcB = (const uint4*)(sb + (2 * lup + 1) * 32 + lhalf * 16);
            uint* dst = &hsh2[(lslice * 4 + lup) * 72 + lhalf * 32];
            #pragma unroll
            for (int g = 0; g < 4; ++g) {
                uint4 A = __ldcg(srcA + g);
                uint4 B = __ldcg(srcB + g);
                uint4 o1, o2;
                o1.x = __byte_perm(A.x, B.x, 0x5410);
                o1.y = __byte_perm(A.x, B.x, 0x7632);
                o1.z = __byte_perm(A.y, B.y, 0x5410);
                o1.w = __byte_perm(A.y, B.y, 0x7632);
                o2.x = __byte_perm(A.z, B.z, 0x5410);
                o2.y = __byte_perm(A.z, B.z, 0x7632);
                o2.z = __byte_perm(A.w, B.w, 0x5410);
                o2.w = __byte_perm(A.w, B.w, 0x7632);
                *(uint4*)(dst + g * 8) = o1;
                *(uint4*)(dst + g * 8 + 4) = o2;
            }
        }
        __syncthreads();

        // gates(16 rows of this m-tile x 16 batches) = W @ h
        float acc0[4] = {0.f, 0.f, 0.f, 0.f};
        float acc1[4] = {0.f, 0.f, 0.f, 0.f};
        #pragma unroll
        for (int kt = 0; kt < KT3; ++kt) {
            const uint* hk = hsh2 + (kt * 8 + ctid) * 72;
            uint b00 = hk[bnw + gid];
            uint b01 = hk[4 * 72 + bnw + gid];
            uint b10 = hk[bnw + 8 + gid];
            uint b11 = hk[4 * 72 + bnw + 8 + gid];
            MMA_BF16(acc0, aw[kt], b00, b01);
            MMA_BF16(acc1, aw[kt], b10, b11);
        }

        // exchange gate pairs with partner (lane ^ 16)
        float s0 = q1 ? acc0[0] : acc1[0];
        float s1 = q1 ? acc0[1] : acc1[1];
        float s2 = q1 ? acc0[2] : acc1[2];
        float s3 = q1 ? acc0[3] : acc1[3];
        float o0 = __shfl_xor_sync(~0u, s0, 16);
        float o1 = __shfl_xor_sync(~0u, s1, 16);
        float o2 = __shfl_xor_sync(~0u, s2, 16);
        float o3 = __shfl_xor_sync(~0u, s3, 16);
        float m0 = q1 ? acc1[0] : acc0[0];
        float m1 = q1 ? acc1[1] : acc0[1];
        float m2 = q1 ? acc1[2] : acc0[2];
        float m3 = q1 ? acc1[3] : acc0[3];
        float gi0 = q1 ? o0 : m0,  gf0 = q1 ? m0 : o0;
        float gg0 = q1 ? o2 : m2,  go0 = q1 ? m2 : o2;
        float gi1 = q1 ? o1 : m1,  gf1 = q1 ? m1 : o1;
        float gg1 = q1 ? o3 : m3,  go1 = q1 ? m3 : o3;

        {
            float cn = sigf(gf0 + bflo(xg[1])) * c0
                     + sigf(gi0 + bflo(xg[0])) * tanhfast(gg0 + bflo(xg[2]));
            float hn = sigf(go0 + bflo(xg[3])) * tanhfast(cn);
            bool valid = (t < len0);
            hp0 = valid ? hn : hp0;
            c0  = valid ? cn : c0;
        }
        {
            float cn = sigf(gf1 + bfhi(xg[1])) * c1
                     + sigf(gi1 + bfhi(xg[0])) * tanhfast(gg1 + bfhi(xg[2]));
            float hn = sigf(go1 + bfhi(xg[3])) * tanhfast(cn);
            bool valid = (t < len1);
            hp1 = valid ? hn : hp1;
            c1  = valid ? cn : c1;
        }

        // broadcast rounded h to history: linear jj*32 + bp layout
        pk = pkbf(hp0, hp1);
        __stcg(hbase + (size_t)ws * HSLOT + ugl * 32 + (b0 >> 1), pk);

        __syncthreads();
        if (tid == 0) {
            asm volatile("fence.acq_rel.gpu;" ::: "memory");
            asm volatile("st.relaxed.gpu.u32 [%0], %1;"
                         :: "l"(flg + sl * 32), "r"((unsigned)(st + 1)) : "memory");
        }

        if (st + 1 < TT) {
            int tn = dir ? (TT - 2 - st) : (st + 1);
            const uint* Gt = Gd + (size_t)tn * G4 * 32;
            #pragma unroll
            for (int q = 0; q < 4; ++q) xg[q] = __ldcg(Gt + goff[q]);
        }
    }
}

// ---------------- K4: FC + log_softmax via bf16 tensor cores (block = one t) ----------------
#define K4SMEM ((64 * 201 + 24 * 201) * 4)
__global__ void __launch_bounds__(128) k4_fc(
    const float* __restrict__ fcw, const float* __restrict__ fcb)
{
    extern __shared__ uint k4u[];
    uint* Ah = k4u;                 // [64][201]
    uint* Bsw = k4u + 64 * 201;     // [24][201]
    __shared__ float fbsh[24];

    int tid = threadIdx.x;
    int t = blockIdx.x;
    int wid = tid >> 5, lane = tid & 31;
    int gid = lane >> 2, ctid = lane & 3;

    for (int i = tid; i < 24 * 200; i += 128) {
        int c = i / 200, j = i % 200;
        uint v = 0u;
        if (c < CC) {
            float w0 = fcw[c * 400 + 2 * j];
            float w1 = fcw[c * 400 + 2 * j + 1];
            v = pkbf(w0, w1);
        }
        Bsw[c * 201 + j] = v;
    }
    if (tid < 24) fbsh[tid] = (tid < CC) ? fcb[tid] : 0.f;

    for (int idx = tid; idx < 6400; idx += 128) {
        int j = idx >> 5, bp = idx & 31;
        int dirr = (j >= 100) ? 1 : 0;
        int jj = 2 * j - dirr * 2 * HH;
        size_t base = (size_t)dirr * HDIR
                    + (size_t)(dirr ? t : (t + 1)) * HSLOT;
        uint U0 = d_hallh[base + jj * 32 + bp];
        uint U1 = d_hallh[base + (jj + 1) * 32 + bp];
        Ah[(2 * bp) * 201 + j]     = __byte_perm(U0, U1, 0x5410);
        Ah[(2 * bp + 1) * 201 + j] = __byte_perm(U0, U1, 0x7632);
    }
    __syncthreads();

    float acc[3][4] = {{0,0,0,0},{0,0,0,0},{0,0,0,0}};
    int mb = wid * 16;
    #pragma unroll 5
    for (int kt = 0; kt < 25; ++kt) {
        uint afr[4];
        const uint* ap = Ah + (mb + gid) * 201 + kt * 8 + ctid;
        afr[0] = ap[0];
        afr[1] = ap[8 * 201];
        afr[2] = ap[4];
        afr[3] = ap[8 * 201 + 4];
        #pragma unroll
        for (int ni = 0; ni < 3; ++ni) {
            const uint* bp_ = Bsw + (ni * 8 + gid) * 201 + kt * 8 + ctid;
            MMA_BF16(acc[ni], afr, bp_[0], bp_[4]);
        }
    }

    #pragma unroll
    for (int rs = 0; rs < 2; ++rs) {
        int b = mb + gid + rs * 8;
        float v[6];
        float mx = -1e30f;
        #pragma unroll
        for (int ni = 0; ni < 3; ++ni) {
            #pragma unroll
            for (int k = 0; k < 2; ++k) {
                int cls = ni * 8 + 2 * ctid + k;
                float x = acc[ni][rs * 2 + k] + fbsh[cls];
                if (cls >= CC) x = -1e30f;
                v[ni * 2 + k] = x;
                mx = fmaxf(mx, x);
            }
        }
        mx = fmaxf(mx, __shfl_xor_sync(~0u, mx, 1));
        mx = fmaxf(mx, __shfl_xor_sync(~0u, mx, 2));
        float s = 0.f;
        #pragma unroll
        for (int k = 0; k < 6; ++k) s += __expf(v[k] - mx);
        s += __shfl_xor_sync(~0u, s, 1);
        s += __shfl_xor_sync(~0u, s, 2);
        float lse = mx + __logf(s);
        #pragma unroll
        for (int ni = 0; ni < 3; ++ni)
            #pragma unroll
            for (int k = 0; k < 2; ++k) {
                int cls = ni * 8 + 2 * ctid + k;
                if (cls < CC)
                    d_logits[((size_t)b * TT + t) * CC + cls] = v[ni * 2 + k] - lse;
            }
    }
}

// ---------------- K5: CRF NLL, exp-factored + lane0-offset logsumexp ----------------
__global__ void __launch_bounds__(32) k5_crf(
    const int* __restrict__ seq_len, const int* __restrict__ target,
    const float* __restrict__ trans, const float* __restrict__ start,
    const float* __restrict__ endsc)
{
    int b = blockIdx.x;
    int lane = threadIdx.x;
    int c = (lane < CC) ? lane : 0;
    int len = seq_len[b];
    const float* L = d_logits + (size_t)b * TT * CC;
    const int* tg = target + (size_t)b * TT;

    float E[CC];
    #pragma unroll
    for (int i = 0; i < CC; ++i)
        E[i] = (lane < CC) ? __expf(trans[i * CC + c]) : 0.f;

    float alpha = (lane < CC) ? (start[c] + L[c]) : -1e30f;
    float emit = (lane < CC && len > 1) ? L[CC + c] : 0.f;

    for (int t = 1; t < len; ++t) {
        float m;
        if ((t & 15) == 1) {
            m = alpha;
            #pragma unroll
            for (int o = 16; o; o >>= 1) m = fmaxf(m, __shfl_xor_sync(~0u, m, o));
        } else {
            m = __shfl_sync(~0u, alpha, 0);
        }
        float p = __expf(alpha - m);
        float sa = 0.f, sb = 0.f, sc = 0.f, sd = 0.f;
        #pragma unroll
        for (int i = 0; i < 5; ++i) {
            sa += __shfl_sync(~0u, p, i)      * E[i];
            sb += __shfl_sync(~0u, p, i + 5)  * E[i + 5];
            sc += __shfl_sync(~0u, p, i + 10) * E[i + 10];
            sd += __shfl_sync(~0u, p, i + 15) * E[i + 15];
        }
        float s = (sa + sb) + (sc + sd);
        float na = m + __logf(s) + emit;
        if (t + 1 < len) emit = (lane < CC) ? L[(t + 1) * CC + c] : 0.f;
        alpha = (lane < CC) ? na : -1e30f;
    }

    float v = (lane < CC) ? (alpha + endsc[c]) : -1e30f;
    float m = v;
    #pragma unroll
    for (int o = 16; o; o >>= 1) m = fmaxf(m, __shfl_xor_sync(~0u, m, o));
    float s = __expf(v - m);
    if (lane >= CC) s = 0.f;
    #pragma unroll
    for (int o = 16; o; o >>= 1) s += __shfl_xor_sync(~0u, s, o);
    float logZ = m + __logf(s);

    float es = 0.f;
    for (int t = lane; t < len; t += 32) es += L[t * CC + tg[t]];
    float ts = 0.f;
    for (int t = lane; t < len - 1; t += 32) ts += trans[tg[t] * CC + tg[t + 1]];
    float g = es + ts;
    #pragma unroll
    for (int o = 16; o; o >>= 1) g += __shfl_xor_sync(~0u, g, o);
    if (lane == 0) {
        float gold = g + start[tg[0]] + endsc[tg[len - 1]];
        d_loss[b] = logZ - gold;
    }
}

// ---------------- K6: mean reduce ----------------
__global__ void __launch_bounds__(64) k6_mean(float* out) {
    __shared__ float sh[64];
    int tid = threadIdx.x;
    sh[tid] = d_loss[tid];
    __syncthreads();
    for (int o = 32; o; o >>= 1) {
        if (tid < o) sh[tid] += sh[tid + o];
        __syncthreads();
    }
    if (tid == 0) out[0] = sh[0] * (1.f / BB);
}

// ---------------- launch ----------------
extern "C" void kernel_launch(void* const* d_in, const int* in_sizes, int n_in,
                              void* d_out, int out_size) {
    const int*   words   = (const int*)d_in[0];
    const int*   seq_len = (const int*)d_in[1];
    const int*   target  = (const int*)d_in[2];
    const float* embed   = (const float*)d_in[3];
    const float* gamma   = (const float*)d_in[4];
    const float* beta    = (const float*)d_in[5];
    const float* wihf    = (const float*)d_in[6];
    const float* whhf    = (const float*)d_in[7];
    const float* bf      = (const float*)d_in[8];
    const float* wihb    = (const float*)d_in[9];
    const float* whhb    = (const float*)d_in[10];
    const float* bb      = (const float*)d_in[11];
    const float* fcw     = (const float*)d_in[12];
    const float* fcb     = (const float*)d_in[13];
    const float* trans   = (const float*)d_in[14];
    const float* startsc = (const float*)d_in[15];
    const float* endsc   = (const float*)d_in[16];
    float* out = (float*)d_out;

    size_t hsmem = (size_t)(104 * 72) * sizeof(uint);   // 29952 B
    cudaFuncSetAttribute(k3_lstm, cudaFuncAttributeMaxDynamicSharedMemorySize,
                         (int)hsmem);
    cudaFuncSetAttribute(k4_fc, cudaFuncAttributeMaxDynamicSharedMemorySize,
                         K4SMEM);

    k1_embed_ln<<<TT * BB / 8, 256>>>(words, embed, gamma, beta);
    {
        dim3 g(2 * G4 / 64, TT * BB / 128);   // 25 x 256
        k2_gemm<<<g, 256>>>(wihf, wihb, bf, bb);
    }
    k3_lstm<<<2 * NBD, 256, hsmem>>>(whhf, whhb, seq_len);
    k4_fc<<<TT, 128, K4SMEM>>>(fcw, fcb);
    k5_crf<<<BB, 32>>>(seq_len, target, trans, startsc, endsc);
    k6_mean<<<1, 64>>>(out);
}